// round 5
// baseline (speedup 1.0000x reference)
#include <cuda_runtime.h>

#define BATCH 16
#define NCH   128
#define TLEN  8192
#define N1    4103
#define N2    2059
#define N3    1037

// ---- scratch (static device arrays; no allocation) --------------------------
__device__ float g_lo1[BATCH * N1 * NCH];   // fwd L1 lo; later inv L2 output y1
__device__ float g_hi1[BATCH * N1 * NCH];
__device__ float g_lo2[BATCH * N2 * NCH];   // fwd L2 lo; later inv L3 output y2
__device__ float g_hi2[BATCH * N2 * NCH];
__device__ float g_lo3[BATCH * N3 * NCH];
__device__ float g_hi3[BATCH * N3 * NCH];
__device__ float g_thr[BATCH * NCH];

// median scratch
#define NSIG   (BATCH * NCH)        // 2048 signals
#define SEG    48                   // candidate slots per (channel, warp-slice)
#define NSLICE 32                   // p-slices per channel
#define CCAP   (SEG * NSLICE)       // 1536
__device__ unsigned int g_cand [NSIG * CCAP];
__device__ int          g_wcnt [NSIG * NSLICE];
__device__ int          g_below[NSIG * 2];

// ---- sym8 filters (compile-time literals -> imm-form FFMA) ------------------
#define FILT_RL {  0.0018899503327594609f, -0.0003029205147241331f, -0.01495225833704823f,   \
                   0.003808752013890615f,   0.049137179673607506f,  -0.027219029917056003f,  \
                  -0.05194583810770904f,    0.36444189483533895f,    0.7771857517005235f,    \
                   0.4813596512583722f,    -0.061273359067658524f,  -0.1432942383508097f,    \
                   0.007607487324917605f,   0.03169508781149298f,   -0.0005421323317911481f, \
                  -0.0033824159510061256f }
#define FILT_RH { -0.0033824159510061256f,  0.0005421323317911481f,  0.03169508781149298f,   \
                  -0.007607487324917605f,  -0.1432942383508097f,     0.061273359067658524f,  \
                   0.4813596512583722f,    -0.7771857517005235f,     0.36444189483533895f,   \
                   0.05194583810770904f,   -0.027219029917056003f,  -0.049137179673607506f,  \
                   0.003808752013890615f,   0.01495225833704823f,   -0.0003029205147241331f, \
                  -0.0018899503327594609f }
#define FILT_DLO { -0.0033824159510061256f, -0.0005421323317911481f,  0.03169508781149298f,  \
                    0.007607487324917605f,  -0.1432942383508097f,    -0.061273359067658524f, \
                    0.4813596512583722f,     0.7771857517005235f,     0.36444189483533895f,  \
                   -0.05194583810770904f,   -0.027219029917056003f,   0.049137179673607506f, \
                    0.003808752013890615f,  -0.01495225833704823f,   -0.0003029205147241331f,\
                    0.0018899503327594609f }
#define FILT_DHI { -0.0018899503327594609f, -0.0003029205147241331f,  0.01495225833704823f,  \
                    0.003808752013890615f,  -0.049137179673607506f,  -0.027219029917056003f, \
                    0.05194583810770904f,    0.36444189483533895f,   -0.7771857517005235f,   \
                    0.4813596512583722f,     0.061273359067658524f,  -0.1432942383508097f,   \
                   -0.007607487324917605f,   0.03169508781149298f,    0.0005421323317911481f,\
                   -0.0033824159510061256f }

// 0.85 / 0.6745 * sqrt(2*log(8192))
#define THRSCALE ((float)(0.85 * 4.2452122112874176 / 0.6745))

#define WLO 0.55f
#define WHI 0.80f
#define KRANK 2051   // 0-based lower-median rank of 4103

#define PF 8
#define PJ 8

// ---- forward analysis: stride-2 16-tap correlation with symmetric pad 14 ----
__global__ __launch_bounds__(256) void fwd_kernel(const float* __restrict__ x0, int level) {
    const float* __restrict__ in;
    float* __restrict__ lo;
    float* __restrict__ hi;
    int nin, nout;
    if (level == 1)      { in = x0;    lo = g_lo1; hi = g_hi1; nin = TLEN; nout = N1; }
    else if (level == 2) { in = g_lo1; lo = g_lo2; hi = g_hi2; nin = N1;   nout = N2; }
    else                 { in = g_lo2; lo = g_lo3; hi = g_hi3; nin = N2;   nout = N3; }

    const int b  = blockIdx.y;
    const int n  = threadIdx.x;
    const int p0 = (blockIdx.x * blockDim.y + threadIdx.y) * PF;
    if (p0 >= nout) return;

    const float RL[16] = FILT_RL;
    const float RH[16] = FILT_RH;

    const float* __restrict__ inb = in + (b * nin) * NCH + n;
    float w[2 * PF + 14];
#pragma unroll
    for (int t = 0; t < 2 * PF + 14; ++t) {
        int i = 2 * p0 - 14 + t;
        if (i < 0)    i = -1 - i;
        if (i >= nin) i = 2 * nin - 1 - i;
        w[t] = inb[i * NCH];
    }

    const int obase = (b * nout + p0) * NCH + n;
#pragma unroll
    for (int e = 0; e < PF; ++e) {
        if (p0 + e < nout) {
            float alo = 0.f, ahi = 0.f;
#pragma unroll
            for (int k = 0; k < 16; ++k) {
                const float v = w[2 * e + k];
                alo += v * RL[k];
                ahi += v * RH[k];
            }
            lo[obase + e * NCH] = alo;
            hi[obase + e * NCH] = ahi;
        }
    }
}

// ---- medA: one streaming pass; count below-window, gather in-window ---------
// grid (4, 16, 2), 512 threads. lane = channel (coalesced), slice = z*16+warp.
__global__ __launch_bounds__(512) void medA_kernel() {
    __shared__ int s_bel[32][17];

    const int lane = threadIdx.x & 31;
    const int w    = threadIdx.x >> 5;          // 0..15
    const int z    = blockIdx.z;                // 0..1
    const int sl   = z * 16 + w;                // slice 0..31
    const int b    = blockIdx.y;
    const int n0   = blockIdx.x * 32;
    const int ch   = b * NCH + n0 + lane;

    const float* __restrict__ base = g_hi1 + (size_t)(b * N1) * NCH + n0 + lane;
    unsigned int* __restrict__ cseg = g_cand + (size_t)ch * CCAP + sl * SEG;

    int below = 0;
    int cnt = 0;
#pragma unroll 4
    for (int p = sl; p < N1; p += NSLICE) {
        const float v = fabsf(base[(size_t)p * NCH]);
        if (v < WLO) below++;
        else if (v < WHI) {
            if (cnt < SEG) cseg[cnt] = __float_as_uint(v);
            cnt++;
        }
    }
    g_wcnt[ch * NSLICE + sl] = cnt;
    s_bel[lane][w] = below;
    __syncthreads();
    if (threadIdx.x < 32) {
        int s = 0;
#pragma unroll
        for (int i = 0; i < 16; ++i) s += s_bel[threadIdx.x][i];
        g_below[(b * NCH + n0 + threadIdx.x) * 2 + z] = s;
    }
}

// ---- medB: per-channel compact + bitonic sort 1024 + rank pick --------------
#define SORTN 1024
__global__ __launch_bounds__(256) void medB_kernel() {
    __shared__ unsigned int sk[SORTN];
    __shared__ int s_off[NSLICE + 1];
    __shared__ int s_flag;
    __shared__ int s_red;

    const int n   = blockIdx.x;
    const int b   = blockIdx.y;
    const int ch  = b * NCH + n;
    const int tid = threadIdx.x;

    // segment counts -> prefix offsets (warp 0)
    if (tid < 32) {
        int L = g_wcnt[ch * NSLICE + tid];
        const unsigned int ov = __ballot_sync(0xffffffffu, L > SEG);
        int incl = L;
#pragma unroll
        for (int d = 1; d < 32; d <<= 1) {
            const int t = __shfl_up_sync(0xffffffffu, incl, d);
            if (tid >= d) incl += t;
        }
        s_off[tid + 1] = incl;
        if (tid == 0) { s_off[0] = 0; s_flag = (ov != 0u); }
    }
    for (int i = tid; i < SORTN; i += 256) sk[i] = 0x7FFFFFFFu;
    __syncthreads();

    const int total = s_off[NSLICE];
    const int below = g_below[ch * 2] + g_below[ch * 2 + 1];
    const int r     = KRANK - below;
    const bool fb   = s_flag || (total > SORTN) || (r < 0) || (r >= total);

    unsigned int result;
    if (!fb) {
        // compact candidates into smem (disjoint ranges; one sync after)
        const unsigned int* __restrict__ cbase = g_cand + (size_t)ch * CCAP;
#pragma unroll 1
        for (int s = 0; s < NSLICE; ++s) {
            const int o = s_off[s];
            const int L = s_off[s + 1] - o;
            for (int i = tid; i < L; i += 256) sk[o + i] = cbase[s * SEG + i];
        }
        __syncthreads();
        // bitonic sort SORTN ascending
        for (int k = 2; k <= SORTN; k <<= 1) {
            for (int j = k >> 1; j > 0; j >>= 1) {
                for (int i = tid; i < SORTN; i += 256) {
                    const int ixj = i ^ j;
                    if (ixj > i) {
                        const unsigned int a = sk[i], c = sk[ixj];
                        const bool up = ((i & k) == 0);
                        if ((a > c) == up) { sk[i] = c; sk[ixj] = a; }
                    }
                }
                __syncthreads();
            }
        }
        result = sk[r];
    } else {
        // exact fallback: 32-step bitwise selection over the full channel
        const float* __restrict__ base = g_hi1 + (size_t)(b * N1) * NCH + n;
        unsigned int prefix = 0u;
        int kk = KRANK;
        for (int bit = 31; bit >= 0; --bit) {
            if (tid == 0) s_red = 0;
            __syncthreads();
            const unsigned int hi = prefix >> bit;   // LSB is 0 (candidate bit = 0)
            int local = 0;
            for (int p = tid; p < N1; p += 256) {
                const unsigned int e = __float_as_uint(fabsf(base[(size_t)p * NCH]));
                if ((e >> bit) == hi) local++;
            }
            atomicAdd(&s_red, local);
            __syncthreads();
            const int c0 = s_red;
            if (kk >= c0) { kk -= c0; prefix |= (1u << bit); }
            __syncthreads();
        }
        result = prefix;
    }
    if (tid == 0) g_thr[ch] = __uint_as_float(result) * THRSCALE;
}

// ---- inverse synthesis: transposed conv, soft-threshold of hi fused --------
__global__ __launch_bounds__(256) void inv_kernel(float* __restrict__ dout, int level) {
    const float* __restrict__ lo;
    const float* __restrict__ hi;
    float* __restrict__ out;
    int n, nout;
    if (level == 3)      { lo = g_lo3; hi = g_hi3; out = g_lo2; n = N3; nout = N2;   }
    else if (level == 2) { lo = g_lo2; hi = g_hi2; out = g_lo1; n = N2; nout = N1;   }
    else                 { lo = g_lo1; hi = g_hi1; out = dout;  n = N1; nout = TLEN; }

    const int b  = blockIdx.y;
    const int nn = threadIdx.x;
    const int j0 = (blockIdx.x * blockDim.y + threadIdx.y) * PJ;
    if (2 * j0 >= nout) return;

    const float thr = g_thr[b * NCH + nn];
    const float DLO[16] = FILT_DLO;
    const float DHI[16] = FILT_DHI;

    const float* __restrict__ lob = lo + (b * n) * NCH + nn;
    const float* __restrict__ hib = hi + (b * n) * NCH + nn;

    float wl[PJ + 7], wh[PJ + 7];
#pragma unroll
    for (int t = 0; t < PJ + 7; ++t) {
        int jj = j0 + t;
        if (jj > n - 1) jj = n - 1;  // clamp: clamped values feed only guarded-off outputs
        wl[t] = lob[jj * NCH];
        const float h = hib[jj * NCH];
        const float a = fabsf(h) - thr;
        wh[t] = (a > 0.f) ? copysignf(a, h) : 0.f;
    }

    const int ob = (b * nout) * NCH + nn;
#pragma unroll
    for (int e = 0; e < PJ; ++e) {
        const int m = 2 * (j0 + e);
        if (m < nout) {
            float a0 = 0.f, a1 = 0.f;
#pragma unroll
            for (int d = 0; d < 8; ++d) {
                a0 += wl[e + d] * DLO[2 * d + 1] + wh[e + d] * DHI[2 * d + 1];
                a1 += wl[e + d] * DLO[2 * d]     + wh[e + d] * DHI[2 * d];
            }
            out[ob + m * NCH] = a0;
            if (m + 1 < nout) out[ob + (m + 1) * NCH] = a1;
        }
    }
}

// ---- launch ----------------------------------------------------------------
extern "C" void kernel_launch(void* const* d_in, const int* in_sizes, int n_in,
                              void* d_out, int out_size) {
    const float* x = (const float*)d_in[0];
    float* out = (float*)d_out;

    const dim3 blk(128, 2);
    fwd_kernel<<<dim3(257, BATCH), blk>>>(x, 1);   // 4103
    fwd_kernel<<<dim3(129, BATCH), blk>>>(x, 2);   // 2059
    fwd_kernel<<<dim3( 65, BATCH), blk>>>(x, 3);   // 1037
    medA_kernel<<<dim3(NCH / 32, BATCH, 2), 512>>>();
    medB_kernel<<<dim3(NCH, BATCH), 256>>>();
    inv_kernel<<<dim3( 65, BATCH), blk>>>(out, 3); // -> N2
    inv_kernel<<<dim3(129, BATCH), blk>>>(out, 2); // -> N1
    inv_kernel<<<dim3(256, BATCH), blk>>>(out, 1); // -> TLEN
}

// round 6
// speedup vs baseline: 1.3950x; 1.3950x over previous
#include <cuda_runtime.h>

#define BATCH 16
#define NCH   128
#define TLEN  8192
#define N1    4103
#define N2    2059
#define N3    1037

// ---- scratch (static device arrays; no allocation) --------------------------
__device__ float g_lo1[BATCH * N1 * NCH];   // fwd L1 lo; later inv L2 output y1
__device__ float g_hi1[BATCH * N1 * NCH];
__device__ float g_lo2[BATCH * N2 * NCH];   // fwd L2 lo; later inv L3 output y2
__device__ float g_hi2[BATCH * N2 * NCH];
__device__ float g_lo3[BATCH * N3 * NCH];
__device__ float g_hi3[BATCH * N3 * NCH];
__device__ float g_thr[BATCH * NCH];

// ---- sym8 filters (compile-time literals -> imm-form FFMA) ------------------
#define FILT_RL {  0.0018899503327594609f, -0.0003029205147241331f, -0.01495225833704823f,   \
                   0.003808752013890615f,   0.049137179673607506f,  -0.027219029917056003f,  \
                  -0.05194583810770904f,    0.36444189483533895f,    0.7771857517005235f,    \
                   0.4813596512583722f,    -0.061273359067658524f,  -0.1432942383508097f,    \
                   0.007607487324917605f,   0.03169508781149298f,   -0.0005421323317911481f, \
                  -0.0033824159510061256f }
#define FILT_RH { -0.0033824159510061256f,  0.0005421323317911481f,  0.03169508781149298f,   \
                  -0.007607487324917605f,  -0.1432942383508097f,     0.061273359067658524f,  \
                   0.4813596512583722f,    -0.7771857517005235f,     0.36444189483533895f,   \
                   0.05194583810770904f,   -0.027219029917056003f,  -0.049137179673607506f,  \
                   0.003808752013890615f,   0.01495225833704823f,   -0.0003029205147241331f, \
                  -0.0018899503327594609f }
#define FILT_DLO { -0.0033824159510061256f, -0.0005421323317911481f,  0.03169508781149298f,  \
                    0.007607487324917605f,  -0.1432942383508097f,    -0.061273359067658524f, \
                    0.4813596512583722f,     0.7771857517005235f,     0.36444189483533895f,  \
                   -0.05194583810770904f,   -0.027219029917056003f,   0.049137179673607506f, \
                    0.003808752013890615f,  -0.01495225833704823f,   -0.0003029205147241331f,\
                    0.0018899503327594609f }
#define FILT_DHI { -0.0018899503327594609f, -0.0003029205147241331f,  0.01495225833704823f,  \
                    0.003808752013890615f,  -0.049137179673607506f,  -0.027219029917056003f, \
                    0.05194583810770904f,    0.36444189483533895f,   -0.7771857517005235f,   \
                    0.4813596512583722f,     0.061273359067658524f,  -0.1432942383508097f,   \
                   -0.007607487324917605f,   0.03169508781149298f,    0.0005421323317911481f,\
                   -0.0033824159510061256f }

// 0.85 / 0.6745 * sqrt(2*log(8192))
#define THRSCALE ((float)(0.85 * 4.2452122112874176 / 0.6745))

#define WLO   0.55f
#define WHI   0.80f
#define MBINS 128
#define MCAP  32
#define KRANK 2051   // 0-based lower-median rank of 4103

#define PF 8
#define PJ 8

// ---- forward analysis: stride-2 16-tap correlation with symmetric pad 14 ----
__global__ __launch_bounds__(256) void fwd_kernel(const float* __restrict__ x0, int level) {
    const float* __restrict__ in;
    float* __restrict__ lo;
    float* __restrict__ hi;
    int nin, nout;
    if (level == 1)      { in = x0;    lo = g_lo1; hi = g_hi1; nin = TLEN; nout = N1; }
    else if (level == 2) { in = g_lo1; lo = g_lo2; hi = g_hi2; nin = N1;   nout = N2; }
    else                 { in = g_lo2; lo = g_lo3; hi = g_hi3; nin = N2;   nout = N3; }

    const int b  = blockIdx.y;
    const int n  = threadIdx.x;
    const int p0 = (blockIdx.x * blockDim.y + threadIdx.y) * PF;
    if (p0 >= nout) return;

    const float RL[16] = FILT_RL;
    const float RH[16] = FILT_RH;

    const float* __restrict__ inb = in + (b * nin) * NCH + n;
    float w[2 * PF + 14];
#pragma unroll
    for (int t = 0; t < 2 * PF + 14; ++t) {
        int i = 2 * p0 - 14 + t;
        if (i < 0)    i = -1 - i;
        if (i >= nin) i = 2 * nin - 1 - i;
        w[t] = inb[i * NCH];
    }

    const int obase = (b * nout + p0) * NCH + n;
#pragma unroll
    for (int e = 0; e < PF; ++e) {
        if (p0 + e < nout) {
            float alo = 0.f, ahi = 0.f;
#pragma unroll
            for (int k = 0; k < 16; ++k) {
                const float v = w[2 * e + k];
                alo += v * RL[k];
                ahi += v * RH[k];
            }
            lo[obase + e * NCH] = alo;
            hi[obase + e * NCH] = ahi;
        }
    }
}

// ---- median of |cd1|: fused histogram-window selection ----------------------
// 1 CTA per 32 channels. lane = channel (coalesced 128B lines), warp = p-slice.
// Pass1: below-count (register) + 128-bin windowed histogram (smem, lane-keyed).
// Scan: per-channel target bin + rank-within-bin. Pass2: collect ~10 bin members,
// exact k-th selection in registers. Bitwise-exact fallback for window misses.
__global__ __launch_bounds__(1024) void med_kernel() {
    __shared__ unsigned int s_hist[MBINS * 32];  // 16 KB
    __shared__ unsigned int s_below[32];
    __shared__ unsigned int s_cand[MCAP * 32];   // 4 KB
    __shared__ unsigned int s_cnt[32];
    __shared__ int s_tbin[32];
    __shared__ int s_krem[32];
    __shared__ unsigned int s_fb;
    __shared__ int s_red;

    const int tid  = threadIdx.x;
    const int lane = tid & 31;
    const int w    = tid >> 5;                  // 0..31
    const int b    = blockIdx.y;
    const int n0   = blockIdx.x * 32;
    const float* __restrict__ base = g_hi1 + (size_t)(b * N1) * NCH + n0 + lane;

    for (int i = tid; i < MBINS * 32; i += 1024) s_hist[i] = 0u;
    if (tid < 32) { s_below[tid] = 0u; s_cnt[tid] = 0u; }
    if (tid == 0) s_fb = 0u;
    __syncthreads();

    // pass 1: batch 4 loads per iteration for MLP
    int below = 0;
#pragma unroll 1
    for (int p = w; p < N1; p += 128) {
        float v0 = fabsf(base[(size_t)p * NCH]);
        float v1 = (p + 32 < N1) ? fabsf(base[(size_t)(p + 32) * NCH]) : 1e9f;
        float v2 = (p + 64 < N1) ? fabsf(base[(size_t)(p + 64) * NCH]) : 1e9f;
        float v3 = (p + 96 < N1) ? fabsf(base[(size_t)(p + 96) * NCH]) : 1e9f;
#pragma unroll
        for (int q = 0; q < 4; ++q) {
            const float v = (q == 0) ? v0 : (q == 1) ? v1 : (q == 2) ? v2 : v3;
            if (v < WLO) below++;
            else if (v < WHI) {
                int bin = (int)((v - WLO) * 512.0f);
                bin = bin > (MBINS - 1) ? (MBINS - 1) : bin;
                atomicAdd(&s_hist[bin * 32 + lane], 1u);
            }
        }
    }
    atomicAdd(&s_below[lane], (unsigned int)below);
    __syncthreads();

    // scan: find target bin per channel
    if (tid < 32) {
        int r = KRANK - (int)s_below[tid];
        int t = -1;
        if (r >= 0) {
            for (int bn = 0; bn < MBINS; ++bn) {
                const int c = (int)s_hist[bn * 32 + tid];
                if (r < c) { t = bn; break; }
                r -= c;
            }
        }
        s_tbin[tid] = t;
        s_krem[tid] = r;
        if (t < 0) atomicOr(&s_fb, 1u << tid);
    }
    __syncthreads();

    // pass 2: collect members of the target bin (mostly L2 hits)
    const int tb = s_tbin[lane];
#pragma unroll 1
    for (int p = w; p < N1; p += 32) {
        const float v = fabsf(base[(size_t)p * NCH]);
        if (v >= WLO && v < WHI) {
            int bin = (int)((v - WLO) * 512.0f);
            bin = bin > (MBINS - 1) ? (MBINS - 1) : bin;
            if (bin == tb) {
                const unsigned int idx = atomicAdd(&s_cnt[lane], 1u);
                if (idx < MCAP) s_cand[idx * 32 + lane] = __float_as_uint(v);
            }
        }
    }
    __syncthreads();

    if (tid < 32 && s_cnt[tid] > MCAP) atomicOr(&s_fb, 1u << tid);
    __syncthreads();
    const unsigned int fb = s_fb;

    // exact k-th (with ties) among <=32 candidates, per lane
    if (tid < 32 && !((fb >> tid) & 1u)) {
        const int c = (int)s_cnt[tid];
        const int k = s_krem[tid];
        unsigned int res = 0u;
        for (int i = 0; i < c; ++i) {
            const unsigned int x = s_cand[i * 32 + tid];
            int lt = 0, le = 0;
            for (int jj = 0; jj < c; ++jj) {
                const unsigned int y = s_cand[jj * 32 + tid];
                lt += (y < x);
                le += (y <= x);
            }
            if (lt <= k && k < le) res = x;
        }
        g_thr[b * NCH + n0 + tid] = __uint_as_float(res) * THRSCALE;
    }
    __syncthreads();

    // fallback: exact 32-step bitwise selection (statistically never taken)
    if (fb) {
        for (int ch = 0; ch < 32; ++ch) {
            if (!((fb >> ch) & 1u)) continue;
            const float* __restrict__ bp = g_hi1 + (size_t)(b * N1) * NCH + n0 + ch;
            unsigned int prefix = 0u;
            int kk = KRANK;
            for (int bit = 31; bit >= 0; --bit) {
                if (tid == 0) s_red = 0;
                __syncthreads();
                const unsigned int hi = prefix >> bit;  // candidate bit = 0
                int local = 0;
                for (int p = tid; p < N1; p += 1024) {
                    const unsigned int e = __float_as_uint(fabsf(bp[(size_t)p * NCH]));
                    if ((e >> bit) == hi) local++;
                }
                atomicAdd(&s_red, local);
                __syncthreads();
                const int c0 = s_red;
                if (kk >= c0) { kk -= c0; prefix |= (1u << bit); }
                __syncthreads();
            }
            if (tid == 0) g_thr[b * NCH + n0 + ch] = __uint_as_float(prefix) * THRSCALE;
        }
    }
}

// ---- inverse synthesis: transposed conv, soft-threshold of hi fused --------
__global__ __launch_bounds__(256) void inv_kernel(float* __restrict__ dout, int level) {
    const float* __restrict__ lo;
    const float* __restrict__ hi;
    float* __restrict__ out;
    int n, nout;
    if (level == 3)      { lo = g_lo3; hi = g_hi3; out = g_lo2; n = N3; nout = N2;   }
    else if (level == 2) { lo = g_lo2; hi = g_hi2; out = g_lo1; n = N2; nout = N1;   }
    else                 { lo = g_lo1; hi = g_hi1; out = dout;  n = N1; nout = TLEN; }

    const int b  = blockIdx.y;
    const int nn = threadIdx.x;
    const int j0 = (blockIdx.x * blockDim.y + threadIdx.y) * PJ;
    if (2 * j0 >= nout) return;

    const float thr = g_thr[b * NCH + nn];
    const float DLO[16] = FILT_DLO;
    const float DHI[16] = FILT_DHI;

    const float* __restrict__ lob = lo + (b * n) * NCH + nn;
    const float* __restrict__ hib = hi + (b * n) * NCH + nn;

    float wl[PJ + 7], wh[PJ + 7];
#pragma unroll
    for (int t = 0; t < PJ + 7; ++t) {
        int jj = j0 + t;
        if (jj > n - 1) jj = n - 1;  // clamp: clamped values feed only guarded-off outputs
        wl[t] = lob[jj * NCH];
        const float h = hib[jj * NCH];
        const float a = fabsf(h) - thr;
        wh[t] = (a > 0.f) ? copysignf(a, h) : 0.f;
    }

    const int ob = (b * nout) * NCH + nn;
#pragma unroll
    for (int e = 0; e < PJ; ++e) {
        const int m = 2 * (j0 + e);
        if (m < nout) {
            float a0 = 0.f, a1 = 0.f;
#pragma unroll
            for (int d = 0; d < 8; ++d) {
                a0 += wl[e + d] * DLO[2 * d + 1] + wh[e + d] * DHI[2 * d + 1];
                a1 += wl[e + d] * DLO[2 * d]     + wh[e + d] * DHI[2 * d];
            }
            out[ob + m * NCH] = a0;
            if (m + 1 < nout) out[ob + (m + 1) * NCH] = a1;
        }
    }
}

// ---- launch ----------------------------------------------------------------
extern "C" void kernel_launch(void* const* d_in, const int* in_sizes, int n_in,
                              void* d_out, int out_size) {
    const float* x = (const float*)d_in[0];
    float* out = (float*)d_out;

    const dim3 blk(128, 2);
    fwd_kernel<<<dim3(257, BATCH), blk>>>(x, 1);   // 4103
    fwd_kernel<<<dim3(129, BATCH), blk>>>(x, 2);   // 2059
    fwd_kernel<<<dim3( 65, BATCH), blk>>>(x, 3);   // 1037
    med_kernel<<<dim3(NCH / 32, BATCH), 1024>>>();
    inv_kernel<<<dim3( 65, BATCH), blk>>>(out, 3); // -> N2
    inv_kernel<<<dim3(129, BATCH), blk>>>(out, 2); // -> N1
    inv_kernel<<<dim3(256, BATCH), blk>>>(out, 1); // -> TLEN
}

// round 7
// speedup vs baseline: 1.8789x; 1.3469x over previous
#include <cuda_runtime.h>

#define BATCH 16
#define NCH   128
#define TLEN  8192
#define N1    4103
#define N2    2059
#define N3    1037

// ---- scratch (static device arrays; no allocation) --------------------------
__device__ float g_lo1[BATCH * N1 * NCH];   // fwd L1 lo; later inv L2 output y1
__device__ float g_hi1[BATCH * N1 * NCH];
__device__ float g_lo2[BATCH * N2 * NCH];   // fwd L2 lo; later inv L3 output y2
__device__ float g_hi2[BATCH * N2 * NCH];
__device__ float g_lo3[BATCH * N3 * NCH];
__device__ float g_hi3[BATCH * N3 * NCH];
__device__ float g_thr[BATCH * NCH];

// ---- sym8 filters (compile-time literals -> imm-form FFMA) ------------------
#define FILT_RL {  0.0018899503327594609f, -0.0003029205147241331f, -0.01495225833704823f,   \
                   0.003808752013890615f,   0.049137179673607506f,  -0.027219029917056003f,  \
                  -0.05194583810770904f,    0.36444189483533895f,    0.7771857517005235f,    \
                   0.4813596512583722f,    -0.061273359067658524f,  -0.1432942383508097f,    \
                   0.007607487324917605f,   0.03169508781149298f,   -0.0005421323317911481f, \
                  -0.0033824159510061256f }
#define FILT_RH { -0.0033824159510061256f,  0.0005421323317911481f,  0.03169508781149298f,   \
                  -0.007607487324917605f,  -0.1432942383508097f,     0.061273359067658524f,  \
                   0.4813596512583722f,    -0.7771857517005235f,     0.36444189483533895f,   \
                   0.05194583810770904f,   -0.027219029917056003f,  -0.049137179673607506f,  \
                   0.003808752013890615f,   0.01495225833704823f,   -0.0003029205147241331f, \
                  -0.0018899503327594609f }
#define FILT_DLO { -0.0033824159510061256f, -0.0005421323317911481f,  0.03169508781149298f,  \
                    0.007607487324917605f,  -0.1432942383508097f,    -0.061273359067658524f, \
                    0.4813596512583722f,     0.7771857517005235f,     0.36444189483533895f,  \
                   -0.05194583810770904f,   -0.027219029917056003f,   0.049137179673607506f, \
                    0.003808752013890615f,  -0.01495225833704823f,   -0.0003029205147241331f,\
                    0.0018899503327594609f }
#define FILT_DHI { -0.0018899503327594609f, -0.0003029205147241331f,  0.01495225833704823f,  \
                    0.003808752013890615f,  -0.049137179673607506f,  -0.027219029917056003f, \
                    0.05194583810770904f,    0.36444189483533895f,   -0.7771857517005235f,   \
                    0.4813596512583722f,     0.061273359067658524f,  -0.1432942383508097f,   \
                   -0.007607487324917605f,   0.03169508781149298f,    0.0005421323317911481f,\
                   -0.0033824159510061256f }

// 0.85 / 0.6745 * sqrt(2*log(8192))
#define THRSCALE ((float)(0.85 * 4.2452122112874176 / 0.6745))

#define WLO   0.55f
#define WHI   0.80f
#define MBINS 128
#define MCAP  32
#define KRANK 2051   // 0-based lower-median rank of 4103

#define PF 8
#define PJ 8

// ---- forward analysis: stride-2 16-tap correlation with symmetric pad 14 ----
__global__ __launch_bounds__(256) void fwd_kernel(const float* __restrict__ x0, int level) {
    const float* __restrict__ in;
    float* __restrict__ lo;
    float* __restrict__ hi;
    int nin, nout;
    if (level == 1)      { in = x0;    lo = g_lo1; hi = g_hi1; nin = TLEN; nout = N1; }
    else if (level == 2) { in = g_lo1; lo = g_lo2; hi = g_hi2; nin = N1;   nout = N2; }
    else                 { in = g_lo2; lo = g_lo3; hi = g_hi3; nin = N2;   nout = N3; }

    const int b  = blockIdx.y;
    const int n  = threadIdx.x;
    const int p0 = (blockIdx.x * blockDim.y + threadIdx.y) * PF;
    if (p0 >= nout) return;

    const float RL[16] = FILT_RL;
    const float RH[16] = FILT_RH;

    const float* __restrict__ inb = in + (b * nin) * NCH + n;
    float w[2 * PF + 14];
#pragma unroll
    for (int t = 0; t < 2 * PF + 14; ++t) {
        int i = 2 * p0 - 14 + t;
        if (i < 0)    i = -1 - i;
        if (i >= nin) i = 2 * nin - 1 - i;
        w[t] = inb[i * NCH];
    }

    const int obase = (b * nout + p0) * NCH + n;
#pragma unroll
    for (int e = 0; e < PF; ++e) {
        if (p0 + e < nout) {
            float alo = 0.f, ahi = 0.f;
#pragma unroll
            for (int k = 0; k < 16; ++k) {
                const float v = w[2 * e + k];
                alo += v * RL[k];
                ahi += v * RH[k];
            }
            lo[obase + e * NCH] = alo;
            hi[obase + e * NCH] = ahi;
        }
    }
}

// ---- median of |cd1|: histogram-window selection, batched streaming loads ---
// 1 CTA per 32 channels. lane = channel (coalesced 128B lines), warp = p-slice.
// Both passes do 8 unconditional clamped LDGs per batch (MLP=8), masks applied
// after the load -> DRAM-latency hiding. Exact selection + bitwise fallback.
__global__ __launch_bounds__(1024) void med_kernel() {
    __shared__ unsigned int s_hist[MBINS * 32];  // 16 KB
    __shared__ unsigned int s_below[32];
    __shared__ unsigned int s_cand[MCAP * 32];   // 4 KB
    __shared__ unsigned int s_cnt[32];
    __shared__ int s_tbin[32];
    __shared__ int s_krem[32];
    __shared__ unsigned int s_fb;
    __shared__ int s_red;

    const int tid  = threadIdx.x;
    const int lane = tid & 31;
    const int r    = tid >> 5;                  // warp-slice 0..31
    const int b    = blockIdx.y;
    const int n0   = blockIdx.x * 32;
    const float* __restrict__ base = g_hi1 + (size_t)(b * N1) * NCH + n0 + lane;

    for (int i = tid; i < MBINS * 32; i += 1024) s_hist[i] = 0u;
    if (tid < 32) { s_below[tid] = 0u; s_cnt[tid] = 0u; }
    if (tid == 0) s_fb = 0u;
    __syncthreads();

    // ---- pass 1: warp r covers p = r + 32*i, i in [0,129); 16 batches of 8 + tail
    int below = 0;
#pragma unroll 1
    for (int it = 0; it < 16; ++it) {
        float v[8];
#pragma unroll
        for (int q = 0; q < 8; ++q) {
            const int p  = r + 32 * (it * 8 + q);
            const int pc = p < N1 ? p : (N1 - 1);
            const float raw = fabsf(__ldg(base + (size_t)pc * NCH));
            v[q] = (p < N1) ? raw : 1e9f;
        }
#pragma unroll
        for (int q = 0; q < 8; ++q) {
            below += (v[q] < WLO) ? 1 : 0;
            if (v[q] >= WLO && v[q] < WHI) {
                int bin = (int)((v[q] - WLO) * 512.0f);
                bin = bin > (MBINS - 1) ? (MBINS - 1) : bin;
                atomicAdd(&s_hist[bin * 32 + lane], 1u);
            }
        }
    }
    {   // tail i = 128 (only warps r < 7 have a valid slot)
        const int p = r + 32 * 128;
        if (p < N1) {
            const float v = fabsf(__ldg(base + (size_t)p * NCH));
            below += (v < WLO) ? 1 : 0;
            if (v >= WLO && v < WHI) {
                int bin = (int)((v - WLO) * 512.0f);
                bin = bin > (MBINS - 1) ? (MBINS - 1) : bin;
                atomicAdd(&s_hist[bin * 32 + lane], 1u);
            }
        }
    }
    atomicAdd(&s_below[lane], (unsigned int)below);
    __syncthreads();

    // ---- scan: find target bin per channel (warp 0, lane = channel)
    if (tid < 32) {
        int rr = KRANK - (int)s_below[tid];
        int t = -1;
        if (rr >= 0) {
            for (int bn = 0; bn < MBINS; ++bn) {
                const int c = (int)s_hist[bn * 32 + tid];
                if (rr < c) { t = bn; break; }
                rr -= c;
            }
        }
        s_tbin[tid] = t;
        s_krem[tid] = rr;
        if (t < 0) atomicOr(&s_fb, 1u << tid);
    }
    __syncthreads();

    // ---- pass 2: collect members of the target bin (mostly L2 hits)
    const int tb = s_tbin[lane];
#pragma unroll 1
    for (int it = 0; it < 16; ++it) {
        float v[8];
#pragma unroll
        for (int q = 0; q < 8; ++q) {
            const int p  = r + 32 * (it * 8 + q);
            const int pc = p < N1 ? p : (N1 - 1);
            const float raw = fabsf(__ldg(base + (size_t)pc * NCH));
            v[q] = (p < N1) ? raw : 1e9f;
        }
#pragma unroll
        for (int q = 0; q < 8; ++q) {
            if (v[q] >= WLO && v[q] < WHI) {
                int bin = (int)((v[q] - WLO) * 512.0f);
                bin = bin > (MBINS - 1) ? (MBINS - 1) : bin;
                if (bin == tb) {
                    const unsigned int idx = atomicAdd(&s_cnt[lane], 1u);
                    if (idx < MCAP) s_cand[idx * 32 + lane] = __float_as_uint(v[q]);
                }
            }
        }
    }
    {   // tail
        const int p = r + 32 * 128;
        if (p < N1) {
            const float v = fabsf(__ldg(base + (size_t)p * NCH));
            if (v >= WLO && v < WHI) {
                int bin = (int)((v - WLO) * 512.0f);
                bin = bin > (MBINS - 1) ? (MBINS - 1) : bin;
                if (bin == tb) {
                    const unsigned int idx = atomicAdd(&s_cnt[lane], 1u);
                    if (idx < MCAP) s_cand[idx * 32 + lane] = __float_as_uint(v);
                }
            }
        }
    }
    __syncthreads();

    if (tid < 32 && s_cnt[tid] > MCAP) atomicOr(&s_fb, 1u << tid);
    __syncthreads();
    const unsigned int fb = s_fb;

    // ---- exact k-th (with ties) among <=32 candidates, per lane
    if (tid < 32 && !((fb >> tid) & 1u)) {
        const int c = (int)s_cnt[tid];
        const int k = s_krem[tid];
        unsigned int res = 0u;
        for (int i = 0; i < c; ++i) {
            const unsigned int x = s_cand[i * 32 + tid];
            int lt = 0, le = 0;
            for (int jj = 0; jj < c; ++jj) {
                const unsigned int y = s_cand[jj * 32 + tid];
                lt += (y < x);
                le += (y <= x);
            }
            if (lt <= k && k < le) res = x;
        }
        g_thr[b * NCH + n0 + tid] = __uint_as_float(res) * THRSCALE;
    }
    __syncthreads();

    // ---- fallback: exact 32-step bitwise selection (statistically never taken)
    if (fb) {
        for (int ch = 0; ch < 32; ++ch) {
            if (!((fb >> ch) & 1u)) continue;
            const float* __restrict__ bp = g_hi1 + (size_t)(b * N1) * NCH + n0 + ch;
            unsigned int prefix = 0u;
            int kk = KRANK;
            for (int bit = 31; bit >= 0; --bit) {
                if (tid == 0) s_red = 0;
                __syncthreads();
                const unsigned int hi = prefix >> bit;  // candidate bit = 0
                int local = 0;
                for (int p = tid; p < N1; p += 1024) {
                    const unsigned int e = __float_as_uint(fabsf(bp[(size_t)p * NCH]));
                    if ((e >> bit) == hi) local++;
                }
                atomicAdd(&s_red, local);
                __syncthreads();
                const int c0 = s_red;
                if (kk >= c0) { kk -= c0; prefix |= (1u << bit); }
                __syncthreads();
            }
            if (tid == 0) g_thr[b * NCH + n0 + ch] = __uint_as_float(prefix) * THRSCALE;
        }
    }
}

// ---- inverse synthesis: transposed conv, soft-threshold of hi fused --------
__global__ __launch_bounds__(256) void inv_kernel(float* __restrict__ dout, int level) {
    const float* __restrict__ lo;
    const float* __restrict__ hi;
    float* __restrict__ out;
    int n, nout;
    if (level == 3)      { lo = g_lo3; hi = g_hi3; out = g_lo2; n = N3; nout = N2;   }
    else if (level == 2) { lo = g_lo2; hi = g_hi2; out = g_lo1; n = N2; nout = N1;   }
    else                 { lo = g_lo1; hi = g_hi1; out = dout;  n = N1; nout = TLEN; }

    const int b  = blockIdx.y;
    const int nn = threadIdx.x;
    const int j0 = (blockIdx.x * blockDim.y + threadIdx.y) * PJ;
    if (2 * j0 >= nout) return;

    const float thr = g_thr[b * NCH + nn];
    const float DLO[16] = FILT_DLO;
    const float DHI[16] = FILT_DHI;

    const float* __restrict__ lob = lo + (b * n) * NCH + nn;
    const float* __restrict__ hib = hi + (b * n) * NCH + nn;

    float wl[PJ + 7], wh[PJ + 7];
#pragma unroll
    for (int t = 0; t < PJ + 7; ++t) {
        int jj = j0 + t;
        if (jj > n - 1) jj = n - 1;  // clamp: clamped values feed only guarded-off outputs
        wl[t] = lob[jj * NCH];
        const float h = hib[jj * NCH];
        const float a = fabsf(h) - thr;
        wh[t] = (a > 0.f) ? copysignf(a, h) : 0.f;
    }

    const int ob = (b * nout) * NCH + nn;
#pragma unroll
    for (int e = 0; e < PJ; ++e) {
        const int m = 2 * (j0 + e);
        if (m < nout) {
            float a0 = 0.f, a1 = 0.f;
#pragma unroll
            for (int d = 0; d < 8; ++d) {
                a0 += wl[e + d] * DLO[2 * d + 1] + wh[e + d] * DHI[2 * d + 1];
                a1 += wl[e + d] * DLO[2 * d]     + wh[e + d] * DHI[2 * d];
            }
            out[ob + m * NCH] = a0;
            if (m + 1 < nout) out[ob + (m + 1) * NCH] = a1;
        }
    }
}

// ---- launch ----------------------------------------------------------------
extern "C" void kernel_launch(void* const* d_in, const int* in_sizes, int n_in,
                              void* d_out, int out_size) {
    const float* x = (const float*)d_in[0];
    float* out = (float*)d_out;

    const dim3 blk(128, 2);
    fwd_kernel<<<dim3(257, BATCH), blk>>>(x, 1);   // 4103
    fwd_kernel<<<dim3(129, BATCH), blk>>>(x, 2);   // 2059
    fwd_kernel<<<dim3( 65, BATCH), blk>>>(x, 3);   // 1037
    med_kernel<<<dim3(NCH / 32, BATCH), 1024>>>();
    inv_kernel<<<dim3( 65, BATCH), blk>>>(out, 3); // -> N2
    inv_kernel<<<dim3(129, BATCH), blk>>>(out, 2); // -> N1
    inv_kernel<<<dim3(256, BATCH), blk>>>(out, 1); // -> TLEN
}

// round 8
// speedup vs baseline: 2.2985x; 1.2233x over previous
#include <cuda_runtime.h>

#define BATCH 16
#define NCH   128
#define TLEN  8192
#define N1    4103
#define N2    2059
#define N3    1037

// ---- scratch (static device arrays; no allocation) --------------------------
__device__ float g_lo1[BATCH * N1 * NCH];   // fwd L1 lo; later inv L2 output y1
__device__ float g_hi1[BATCH * N1 * NCH];
__device__ float g_lo2[BATCH * N2 * NCH];   // fwd L2 lo; later inv L3 output y2
__device__ float g_hi2[BATCH * N2 * NCH];
__device__ float g_lo3[BATCH * N3 * NCH];
__device__ float g_hi3[BATCH * N3 * NCH];
__device__ float g_thr[BATCH * NCH];

// ---- sym8 filters (compile-time literals -> imm-form FFMA) ------------------
#define FILT_RL {  0.0018899503327594609f, -0.0003029205147241331f, -0.01495225833704823f,   \
                   0.003808752013890615f,   0.049137179673607506f,  -0.027219029917056003f,  \
                  -0.05194583810770904f,    0.36444189483533895f,    0.7771857517005235f,    \
                   0.4813596512583722f,    -0.061273359067658524f,  -0.1432942383508097f,    \
                   0.007607487324917605f,   0.03169508781149298f,   -0.0005421323317911481f, \
                  -0.0033824159510061256f }
#define FILT_RH { -0.0033824159510061256f,  0.0005421323317911481f,  0.03169508781149298f,   \
                  -0.007607487324917605f,  -0.1432942383508097f,     0.061273359067658524f,  \
                   0.4813596512583722f,    -0.7771857517005235f,     0.36444189483533895f,   \
                   0.05194583810770904f,   -0.027219029917056003f,  -0.049137179673607506f,  \
                   0.003808752013890615f,   0.01495225833704823f,   -0.0003029205147241331f, \
                  -0.0018899503327594609f }
#define FILT_DLO { -0.0033824159510061256f, -0.0005421323317911481f,  0.03169508781149298f,  \
                    0.007607487324917605f,  -0.1432942383508097f,    -0.061273359067658524f, \
                    0.4813596512583722f,     0.7771857517005235f,     0.36444189483533895f,  \
                   -0.05194583810770904f,   -0.027219029917056003f,   0.049137179673607506f, \
                    0.003808752013890615f,  -0.01495225833704823f,   -0.0003029205147241331f,\
                    0.0018899503327594609f }
#define FILT_DHI { -0.0018899503327594609f, -0.0003029205147241331f,  0.01495225833704823f,  \
                    0.003808752013890615f,  -0.049137179673607506f,  -0.027219029917056003f, \
                    0.05194583810770904f,    0.36444189483533895f,   -0.7771857517005235f,   \
                    0.4813596512583722f,     0.061273359067658524f,  -0.1432942383508097f,   \
                   -0.007607487324917605f,   0.03169508781149298f,    0.0005421323317911481f,\
                   -0.0033824159510061256f }

// 0.85 / 0.6745 * sqrt(2*log(8192))
#define THRSCALE ((float)(0.85 * 4.2452122112874176 / 0.6745))

#define WLO   0.55f
#define WHI   0.80f
#define MBINS 128
#define MCAP  32
#define KRANK 2051   // 0-based lower-median rank of 4103

#define PF 8
#define PJ 8

// ---- forward analysis: stride-2 16-tap correlation with symmetric pad 14 ----
__global__ __launch_bounds__(256) void fwd_kernel(const float* __restrict__ x0, int level) {
    const float* __restrict__ in;
    float* __restrict__ lo;
    float* __restrict__ hi;
    int nin, nout;
    if (level == 1)      { in = x0;    lo = g_lo1; hi = g_hi1; nin = TLEN; nout = N1; }
    else if (level == 2) { in = g_lo1; lo = g_lo2; hi = g_hi2; nin = N1;   nout = N2; }
    else                 { in = g_lo2; lo = g_lo3; hi = g_hi3; nin = N2;   nout = N3; }

    const int b  = blockIdx.y;
    const int n  = threadIdx.x;
    const int p0 = (blockIdx.x * blockDim.y + threadIdx.y) * PF;
    if (p0 >= nout) return;

    const float RL[16] = FILT_RL;
    const float RH[16] = FILT_RH;

    const float* __restrict__ inb = in + (b * nin) * NCH + n;
    float w[2 * PF + 14];
#pragma unroll
    for (int t = 0; t < 2 * PF + 14; ++t) {
        int i = 2 * p0 - 14 + t;
        if (i < 0)    i = -1 - i;
        if (i >= nin) i = 2 * nin - 1 - i;
        w[t] = inb[i * NCH];
    }

    const int obase = (b * nout + p0) * NCH + n;
#pragma unroll
    for (int e = 0; e < PF; ++e) {
        if (p0 + e < nout) {
            float alo = 0.f, ahi = 0.f;
#pragma unroll
            for (int k = 0; k < 16; ++k) {
                const float v = w[2 * e + k];
                alo += v * RL[k];
                ahi += v * RH[k];
            }
            lo[obase + e * NCH] = alo;
            hi[obase + e * NCH] = ahi;
        }
    }
}

// ---- median of |cd1|: histogram-window selection, 8 channels/CTA ------------
// grid (16,16) = 256 CTAs -> all SMs. Per warp: 4 p-slices x 8 channels, so
// every LDG is 4x32B sectors. Batched unconditional clamped loads (MLP=8).
#define CPC   8                      // channels per CTA
#define HPAD  9                      // hist stride (bank spread)
__global__ __launch_bounds__(1024) void med_kernel() {
    __shared__ unsigned int s_hist[MBINS * HPAD];   // 4.6 KB
    __shared__ unsigned int s_below[CPC];
    __shared__ unsigned int s_cand[MCAP * CPC];
    __shared__ unsigned int s_cnt[CPC];
    __shared__ int s_tbin[CPC];
    __shared__ int s_krem[CPC];
    __shared__ unsigned int s_fb;
    __shared__ int s_red;

    const int tid   = threadIdx.x;
    const int lane  = tid & 31;
    const int ch    = tid & (CPC - 1);
    const int slice = tid >> 3;                 // 0..127
    const int b     = blockIdx.y;
    const int n0    = blockIdx.x * CPC;
    const float* __restrict__ base = g_hi1 + (size_t)(b * N1) * NCH + n0 + ch;

    for (int i = tid; i < MBINS * HPAD; i += 1024) s_hist[i] = 0u;
    if (tid < CPC) { s_below[tid] = 0u; s_cnt[tid] = 0u; }
    if (tid == 0) s_fb = 0u;
    __syncthreads();

    // ---- pass 1: slice covers p = slice + 128*i, i in [0,32) + tail i=32
    int below = 0;
#pragma unroll 1
    for (int it = 0; it < 4; ++it) {
        float v[8];
#pragma unroll
        for (int q = 0; q < 8; ++q) {
            const int p = slice + 128 * (it * 8 + q);   // < 4096 always
            v[q] = fabsf(__ldg(base + (size_t)p * NCH));
        }
#pragma unroll
        for (int q = 0; q < 8; ++q) {
            below += (v[q] < WLO) ? 1 : 0;
            if (v[q] >= WLO && v[q] < WHI) {
                int bin = (int)((v[q] - WLO) * 512.0f);
                bin = bin > (MBINS - 1) ? (MBINS - 1) : bin;
                atomicAdd(&s_hist[bin * HPAD + ch], 1u);
            }
        }
    }
    {   // tail: p = slice + 4096, valid for slice < 7
        const int p = slice + 4096;
        if (p < N1) {
            const float v = fabsf(__ldg(base + (size_t)p * NCH));
            below += (v < WLO) ? 1 : 0;
            if (v >= WLO && v < WHI) {
                int bin = (int)((v - WLO) * 512.0f);
                bin = bin > (MBINS - 1) ? (MBINS - 1) : bin;
                atomicAdd(&s_hist[bin * HPAD + ch], 1u);
            }
        }
    }
    // warp-reduce below across the 4 slices sharing a channel, then 8 atomics
    below += __shfl_down_sync(0xffffffffu, below, 16);
    below += __shfl_down_sync(0xffffffffu, below, 8);
    if (lane < CPC) atomicAdd(&s_below[lane], (unsigned int)below);
    __syncthreads();

    // ---- scan: target bin per channel
    if (tid < CPC) {
        int rr = KRANK - (int)s_below[tid];
        int t = -1;
        if (rr >= 0) {
            for (int bn = 0; bn < MBINS; ++bn) {
                const int c = (int)s_hist[bn * HPAD + tid];
                if (rr < c) { t = bn; break; }
                rr -= c;
            }
        }
        s_tbin[tid] = t;
        s_krem[tid] = rr;
        if (t < 0) atomicOr(&s_fb, 1u << tid);
    }
    __syncthreads();

    // ---- pass 2: collect members of the target bin (L2 hits)
    const int tb = s_tbin[ch];
#pragma unroll 1
    for (int it = 0; it < 4; ++it) {
        float v[8];
#pragma unroll
        for (int q = 0; q < 8; ++q) {
            const int p = slice + 128 * (it * 8 + q);
            v[q] = fabsf(__ldg(base + (size_t)p * NCH));
        }
#pragma unroll
        for (int q = 0; q < 8; ++q) {
            if (v[q] >= WLO && v[q] < WHI) {
                int bin = (int)((v[q] - WLO) * 512.0f);
                bin = bin > (MBINS - 1) ? (MBINS - 1) : bin;
                if (bin == tb) {
                    const unsigned int idx = atomicAdd(&s_cnt[ch], 1u);
                    if (idx < MCAP) s_cand[idx * CPC + ch] = __float_as_uint(v[q]);
                }
            }
        }
    }
    {   // tail
        const int p = slice + 4096;
        if (p < N1) {
            const float v = fabsf(__ldg(base + (size_t)p * NCH));
            if (v >= WLO && v < WHI) {
                int bin = (int)((v - WLO) * 512.0f);
                bin = bin > (MBINS - 1) ? (MBINS - 1) : bin;
                if (bin == tb) {
                    const unsigned int idx = atomicAdd(&s_cnt[ch], 1u);
                    if (idx < MCAP) s_cand[idx * CPC + ch] = __float_as_uint(v);
                }
            }
        }
    }
    __syncthreads();

    if (tid < CPC && s_cnt[tid] > MCAP) atomicOr(&s_fb, 1u << tid);
    __syncthreads();
    const unsigned int fb = s_fb;

    // ---- exact k-th (with ties) among <=32 candidates, per channel
    if (tid < CPC && !((fb >> tid) & 1u)) {
        const int c = (int)s_cnt[tid];
        const int k = s_krem[tid];
        unsigned int res = 0u;
        for (int i = 0; i < c; ++i) {
            const unsigned int x = s_cand[i * CPC + tid];
            int lt = 0, le = 0;
            for (int jj = 0; jj < c; ++jj) {
                const unsigned int y = s_cand[jj * CPC + tid];
                lt += (y < x);
                le += (y <= x);
            }
            if (lt <= k && k < le) res = x;
        }
        g_thr[b * NCH + n0 + tid] = __uint_as_float(res) * THRSCALE;
    }
    __syncthreads();

    // ---- fallback: exact 32-step bitwise selection (statistically never taken)
    if (fb) {
        for (int c2 = 0; c2 < CPC; ++c2) {
            if (!((fb >> c2) & 1u)) continue;
            const float* __restrict__ bp = g_hi1 + (size_t)(b * N1) * NCH + n0 + c2;
            unsigned int prefix = 0u;
            int kk = KRANK;
            for (int bit = 31; bit >= 0; --bit) {
                if (tid == 0) s_red = 0;
                __syncthreads();
                const unsigned int hi = prefix >> bit;  // candidate bit = 0
                int local = 0;
                for (int p = tid; p < N1; p += 1024) {
                    const unsigned int e = __float_as_uint(fabsf(bp[(size_t)p * NCH]));
                    if ((e >> bit) == hi) local++;
                }
                atomicAdd(&s_red, local);
                __syncthreads();
                const int c0 = s_red;
                if (kk >= c0) { kk -= c0; prefix |= (1u << bit); }
                __syncthreads();
            }
            if (tid == 0) g_thr[b * NCH + n0 + c2] = __uint_as_float(prefix) * THRSCALE;
        }
    }
}

// ---- inverse synthesis: transposed conv, soft-threshold of hi fused --------
__global__ __launch_bounds__(256) void inv_kernel(float* __restrict__ dout, int level) {
    const float* __restrict__ lo;
    const float* __restrict__ hi;
    float* __restrict__ out;
    int n, nout;
    if (level == 3)      { lo = g_lo3; hi = g_hi3; out = g_lo2; n = N3; nout = N2;   }
    else if (level == 2) { lo = g_lo2; hi = g_hi2; out = g_lo1; n = N2; nout = N1;   }
    else                 { lo = g_lo1; hi = g_hi1; out = dout;  n = N1; nout = TLEN; }

    const int b  = blockIdx.y;
    const int nn = threadIdx.x;
    const int j0 = (blockIdx.x * blockDim.y + threadIdx.y) * PJ;
    if (2 * j0 >= nout) return;

    const float thr = g_thr[b * NCH + nn];
    const float DLO[16] = FILT_DLO;
    const float DHI[16] = FILT_DHI;

    const float* __restrict__ lob = lo + (b * n) * NCH + nn;
    const float* __restrict__ hib = hi + (b * n) * NCH + nn;

    float wl[PJ + 7], wh[PJ + 7];
#pragma unroll
    for (int t = 0; t < PJ + 7; ++t) {
        int jj = j0 + t;
        if (jj > n - 1) jj = n - 1;  // clamp: clamped values feed only guarded-off outputs
        wl[t] = lob[jj * NCH];
        const float h = hib[jj * NCH];
        const float a = fabsf(h) - thr;
        wh[t] = (a > 0.f) ? copysignf(a, h) : 0.f;
    }

    const int ob = (b * nout) * NCH + nn;
#pragma unroll
    for (int e = 0; e < PJ; ++e) {
        const int m = 2 * (j0 + e);
        if (m < nout) {
            float a0 = 0.f, a1 = 0.f;
#pragma unroll
            for (int d = 0; d < 8; ++d) {
                a0 += wl[e + d] * DLO[2 * d + 1] + wh[e + d] * DHI[2 * d + 1];
                a1 += wl[e + d] * DLO[2 * d]     + wh[e + d] * DHI[2 * d];
            }
            out[ob + m * NCH] = a0;
            if (m + 1 < nout) out[ob + (m + 1) * NCH] = a1;
        }
    }
}

// ---- launch ----------------------------------------------------------------
// Dependency chain: fwd1 -> { med || (fwd2 -> fwd3) } -> inv3 -> inv2 -> inv1.
// med only reads g_hi1 / writes g_thr, so it overlaps fwd2/fwd3 on a second
// stream via the capture-legal event fork/join pattern.
extern "C" void kernel_launch(void* const* d_in, const int* in_sizes, int n_in,
                              void* d_out, int out_size) {
    const float* x = (const float*)d_in[0];
    float* out = (float*)d_out;

    static cudaStream_t s2 = nullptr;
    static cudaEvent_t evF = nullptr, evJ = nullptr;
    if (s2 == nullptr) {
        cudaStreamCreateWithFlags(&s2, cudaStreamNonBlocking);
        cudaEventCreateWithFlags(&evF, cudaEventDisableTiming);
        cudaEventCreateWithFlags(&evJ, cudaEventDisableTiming);
    }

    const dim3 blk(128, 2);
    fwd_kernel<<<dim3(257, BATCH), blk>>>(x, 1);   // 4103

    cudaEventRecord(evF, 0);
    cudaStreamWaitEvent(s2, evF, 0);
    med_kernel<<<dim3(NCH / CPC, BATCH), 1024, 0, s2>>>();
    cudaEventRecord(evJ, s2);

    fwd_kernel<<<dim3(129, BATCH), blk>>>(x, 2);   // 2059
    fwd_kernel<<<dim3( 65, BATCH), blk>>>(x, 3);   // 1037

    cudaStreamWaitEvent(0, evJ, 0);
    inv_kernel<<<dim3( 65, BATCH), blk>>>(out, 3); // -> N2
    inv_kernel<<<dim3(129, BATCH), blk>>>(out, 2); // -> N1
    inv_kernel<<<dim3(256, BATCH), blk>>>(out, 1); // -> TLEN
}

// round 9
// speedup vs baseline: 2.7094x; 1.1788x over previous
#include <cuda_runtime.h>

#define BATCH 16
#define NCH   128
#define TLEN  8192
#define N1    4103
#define N2    2059
#define N3    1037

// ---- scratch (static device arrays; no allocation) --------------------------
__device__ float g_lo1[BATCH * N1 * NCH];   // fwd L1 lo; later inv L2 output y1
__device__ float g_hi1[BATCH * N1 * NCH];
__device__ float g_lo2[BATCH * N2 * NCH];   // fwd L2 lo; later inv L3 output y2
__device__ float g_hi2[BATCH * N2 * NCH];
__device__ float g_lo3[BATCH * N3 * NCH];
__device__ float g_hi3[BATCH * N3 * NCH];
__device__ float g_thr[BATCH * NCH];

// ---- sym8 filters (compile-time literals -> imm-form FFMA) ------------------
#define FILT_RL {  0.0018899503327594609f, -0.0003029205147241331f, -0.01495225833704823f,   \
                   0.003808752013890615f,   0.049137179673607506f,  -0.027219029917056003f,  \
                  -0.05194583810770904f,    0.36444189483533895f,    0.7771857517005235f,    \
                   0.4813596512583722f,    -0.061273359067658524f,  -0.1432942383508097f,    \
                   0.007607487324917605f,   0.03169508781149298f,   -0.0005421323317911481f, \
                  -0.0033824159510061256f }
#define FILT_RH { -0.0033824159510061256f,  0.0005421323317911481f,  0.03169508781149298f,   \
                  -0.007607487324917605f,  -0.1432942383508097f,     0.061273359067658524f,  \
                   0.4813596512583722f,    -0.7771857517005235f,     0.36444189483533895f,   \
                   0.05194583810770904f,   -0.027219029917056003f,  -0.049137179673607506f,  \
                   0.003808752013890615f,   0.01495225833704823f,   -0.0003029205147241331f, \
                  -0.0018899503327594609f }
#define FILT_DLO { -0.0033824159510061256f, -0.0005421323317911481f,  0.03169508781149298f,  \
                    0.007607487324917605f,  -0.1432942383508097f,    -0.061273359067658524f, \
                    0.4813596512583722f,     0.7771857517005235f,     0.36444189483533895f,  \
                   -0.05194583810770904f,   -0.027219029917056003f,   0.049137179673607506f, \
                    0.003808752013890615f,  -0.01495225833704823f,   -0.0003029205147241331f,\
                    0.0018899503327594609f }
#define FILT_DHI { -0.0018899503327594609f, -0.0003029205147241331f,  0.01495225833704823f,  \
                    0.003808752013890615f,  -0.049137179673607506f,  -0.027219029917056003f, \
                    0.05194583810770904f,    0.36444189483533895f,   -0.7771857517005235f,   \
                    0.4813596512583722f,     0.061273359067658524f,  -0.1432942383508097f,   \
                   -0.007607487324917605f,   0.03169508781149298f,    0.0005421323317911481f,\
                   -0.0033824159510061256f }

// 0.85 / 0.6745 * sqrt(2*log(8192))
#define THRSCALE ((float)(0.85 * 4.2452122112874176 / 0.6745))

#define WLO   0.55f
#define WHI   0.80f
#define MBINS 128
#define MCAP  32
#define KRANK 2051   // 0-based lower-median rank of 4103

#define PF 8
#define PJ 8

// ---- forward analysis: stride-2 16-tap correlation with symmetric pad 14 ----
// Interior tiles take a fast path: one base pointer + compile-time immediate
// offsets (t*NCH), no reflection tests, no store guards -> minimal ALU.
__global__ __launch_bounds__(256) void fwd_kernel(const float* __restrict__ x0, int level) {
    const float* __restrict__ in;
    float* __restrict__ lo;
    float* __restrict__ hi;
    int nin, nout;
    if (level == 1)      { in = x0;    lo = g_lo1; hi = g_hi1; nin = TLEN; nout = N1; }
    else if (level == 2) { in = g_lo1; lo = g_lo2; hi = g_hi2; nin = N1;   nout = N2; }
    else                 { in = g_lo2; lo = g_lo3; hi = g_hi3; nin = N2;   nout = N3; }

    const int b  = blockIdx.y;
    const int n  = threadIdx.x;
    const int p0 = (blockIdx.x * blockDim.y + threadIdx.y) * PF;
    if (p0 >= nout) return;

    const float RL[16] = FILT_RL;
    const float RH[16] = FILT_RH;

    const float* __restrict__ inb = in + (size_t)(b * nin) * NCH + n;
    const size_t obase = (size_t)(b * nout + p0) * NCH + n;

    float w[2 * PF + 14];
    const bool interior = (p0 >= 7) && (2 * p0 + 15 < nin) && (p0 + PF <= nout);

    if (interior) {
        const float* __restrict__ q = inb + (size_t)(2 * p0 - 14) * NCH;
#pragma unroll
        for (int t = 0; t < 2 * PF + 14; ++t)
            w[t] = q[(size_t)t * NCH];                 // immediate offsets

        float* __restrict__ lop = lo + obase;
        float* __restrict__ hip = hi + obase;
#pragma unroll
        for (int e = 0; e < PF; ++e) {
            float alo = 0.f, ahi = 0.f;
#pragma unroll
            for (int k = 0; k < 16; ++k) {
                const float v = w[2 * e + k];
                alo += v * RL[k];
                ahi += v * RH[k];
            }
            lop[(size_t)e * NCH] = alo;                // immediate offsets
            hip[(size_t)e * NCH] = ahi;
        }
    } else {
#pragma unroll
        for (int t = 0; t < 2 * PF + 14; ++t) {
            int i = 2 * p0 - 14 + t;
            if (i < 0)    i = -1 - i;
            if (i >= nin) i = 2 * nin - 1 - i;
            w[t] = inb[(size_t)i * NCH];
        }
#pragma unroll
        for (int e = 0; e < PF; ++e) {
            if (p0 + e < nout) {
                float alo = 0.f, ahi = 0.f;
#pragma unroll
                for (int k = 0; k < 16; ++k) {
                    const float v = w[2 * e + k];
                    alo += v * RL[k];
                    ahi += v * RH[k];
                }
                lo[obase + (size_t)e * NCH] = alo;
                hi[obase + (size_t)e * NCH] = ahi;
            }
        }
    }
}

// ---- median of |cd1|: histogram-window selection, 8 channels/CTA ------------
#define CPC   8
#define HPAD  9
__global__ __launch_bounds__(1024) void med_kernel() {
    __shared__ unsigned int s_hist[MBINS * HPAD];
    __shared__ unsigned int s_below[CPC];
    __shared__ unsigned int s_cand[MCAP * CPC];
    __shared__ unsigned int s_cnt[CPC];
    __shared__ int s_tbin[CPC];
    __shared__ int s_krem[CPC];
    __shared__ unsigned int s_fb;
    __shared__ int s_red;

    const int tid   = threadIdx.x;
    const int lane  = tid & 31;
    const int ch    = tid & (CPC - 1);
    const int slice = tid >> 3;
    const int b     = blockIdx.y;
    const int n0    = blockIdx.x * CPC;
    const float* __restrict__ base = g_hi1 + (size_t)(b * N1) * NCH + n0 + ch;

    for (int i = tid; i < MBINS * HPAD; i += 1024) s_hist[i] = 0u;
    if (tid < CPC) { s_below[tid] = 0u; s_cnt[tid] = 0u; }
    if (tid == 0) s_fb = 0u;
    __syncthreads();

    int below = 0;
#pragma unroll 1
    for (int it = 0; it < 4; ++it) {
        float v[8];
#pragma unroll
        for (int q = 0; q < 8; ++q) {
            const int p = slice + 128 * (it * 8 + q);
            v[q] = fabsf(__ldg(base + (size_t)p * NCH));
        }
#pragma unroll
        for (int q = 0; q < 8; ++q) {
            below += (v[q] < WLO) ? 1 : 0;
            if (v[q] >= WLO && v[q] < WHI) {
                int bin = (int)((v[q] - WLO) * 512.0f);
                bin = bin > (MBINS - 1) ? (MBINS - 1) : bin;
                atomicAdd(&s_hist[bin * HPAD + ch], 1u);
            }
        }
    }
    {
        const int p = slice + 4096;
        if (p < N1) {
            const float v = fabsf(__ldg(base + (size_t)p * NCH));
            below += (v < WLO) ? 1 : 0;
            if (v >= WLO && v < WHI) {
                int bin = (int)((v - WLO) * 512.0f);
                bin = bin > (MBINS - 1) ? (MBINS - 1) : bin;
                atomicAdd(&s_hist[bin * HPAD + ch], 1u);
            }
        }
    }
    below += __shfl_down_sync(0xffffffffu, below, 16);
    below += __shfl_down_sync(0xffffffffu, below, 8);
    if (lane < CPC) atomicAdd(&s_below[lane], (unsigned int)below);
    __syncthreads();

    if (tid < CPC) {
        int rr = KRANK - (int)s_below[tid];
        int t = -1;
        if (rr >= 0) {
            for (int bn = 0; bn < MBINS; ++bn) {
                const int c = (int)s_hist[bn * HPAD + tid];
                if (rr < c) { t = bn; break; }
                rr -= c;
            }
        }
        s_tbin[tid] = t;
        s_krem[tid] = rr;
        if (t < 0) atomicOr(&s_fb, 1u << tid);
    }
    __syncthreads();

    const int tb = s_tbin[ch];
#pragma unroll 1
    for (int it = 0; it < 4; ++it) {
        float v[8];
#pragma unroll
        for (int q = 0; q < 8; ++q) {
            const int p = slice + 128 * (it * 8 + q);
            v[q] = fabsf(__ldg(base + (size_t)p * NCH));
        }
#pragma unroll
        for (int q = 0; q < 8; ++q) {
            if (v[q] >= WLO && v[q] < WHI) {
                int bin = (int)((v[q] - WLO) * 512.0f);
                bin = bin > (MBINS - 1) ? (MBINS - 1) : bin;
                if (bin == tb) {
                    const unsigned int idx = atomicAdd(&s_cnt[ch], 1u);
                    if (idx < MCAP) s_cand[idx * CPC + ch] = __float_as_uint(v[q]);
                }
            }
        }
    }
    {
        const int p = slice + 4096;
        if (p < N1) {
            const float v = fabsf(__ldg(base + (size_t)p * NCH));
            if (v >= WLO && v < WHI) {
                int bin = (int)((v - WLO) * 512.0f);
                bin = bin > (MBINS - 1) ? (MBINS - 1) : bin;
                if (bin == tb) {
                    const unsigned int idx = atomicAdd(&s_cnt[ch], 1u);
                    if (idx < MCAP) s_cand[idx * CPC + ch] = __float_as_uint(v);
                }
            }
        }
    }
    __syncthreads();

    if (tid < CPC && s_cnt[tid] > MCAP) atomicOr(&s_fb, 1u << tid);
    __syncthreads();
    const unsigned int fb = s_fb;

    if (tid < CPC && !((fb >> tid) & 1u)) {
        const int c = (int)s_cnt[tid];
        const int k = s_krem[tid];
        unsigned int res = 0u;
        for (int i = 0; i < c; ++i) {
            const unsigned int x = s_cand[i * CPC + tid];
            int lt = 0, le = 0;
            for (int jj = 0; jj < c; ++jj) {
                const unsigned int y = s_cand[jj * CPC + tid];
                lt += (y < x);
                le += (y <= x);
            }
            if (lt <= k && k < le) res = x;
        }
        g_thr[b * NCH + n0 + tid] = __uint_as_float(res) * THRSCALE;
    }
    __syncthreads();

    if (fb) {
        for (int c2 = 0; c2 < CPC; ++c2) {
            if (!((fb >> c2) & 1u)) continue;
            const float* __restrict__ bp = g_hi1 + (size_t)(b * N1) * NCH + n0 + c2;
            unsigned int prefix = 0u;
            int kk = KRANK;
            for (int bit = 31; bit >= 0; --bit) {
                if (tid == 0) s_red = 0;
                __syncthreads();
                const unsigned int hi = prefix >> bit;
                int local = 0;
                for (int p = tid; p < N1; p += 1024) {
                    const unsigned int e = __float_as_uint(fabsf(bp[(size_t)p * NCH]));
                    if ((e >> bit) == hi) local++;
                }
                atomicAdd(&s_red, local);
                __syncthreads();
                const int c0 = s_red;
                if (kk >= c0) { kk -= c0; prefix |= (1u << bit); }
                __syncthreads();
            }
            if (tid == 0) g_thr[b * NCH + n0 + c2] = __uint_as_float(prefix) * THRSCALE;
        }
    }
}

// ---- inverse synthesis: transposed conv, soft-threshold of hi fused --------
// Interior tiles: base pointer + immediate offsets, no clamps, no store guards.
__global__ __launch_bounds__(256) void inv_kernel(float* __restrict__ dout, int level) {
    const float* __restrict__ lo;
    const float* __restrict__ hi;
    float* __restrict__ out;
    int n, nout;
    if (level == 3)      { lo = g_lo3; hi = g_hi3; out = g_lo2; n = N3; nout = N2;   }
    else if (level == 2) { lo = g_lo2; hi = g_hi2; out = g_lo1; n = N2; nout = N1;   }
    else                 { lo = g_lo1; hi = g_hi1; out = dout;  n = N1; nout = TLEN; }

    const int b  = blockIdx.y;
    const int nn = threadIdx.x;
    const int j0 = (blockIdx.x * blockDim.y + threadIdx.y) * PJ;
    if (2 * j0 >= nout) return;

    const float thr = g_thr[b * NCH + nn];
    const float DLO[16] = FILT_DLO;
    const float DHI[16] = FILT_DHI;

    const float* __restrict__ lob = lo + (size_t)(b * n) * NCH + nn;
    const float* __restrict__ hib = hi + (size_t)(b * n) * NCH + nn;
    const size_t ob = (size_t)(b * nout) * NCH + nn;

    float wl[PJ + 7], wh[PJ + 7];
    const bool interior = (j0 + PJ + 6 < n) && (2 * (j0 + PJ) <= nout);

    if (interior) {
        const float* __restrict__ lq = lob + (size_t)j0 * NCH;
        const float* __restrict__ hq = hib + (size_t)j0 * NCH;
#pragma unroll
        for (int t = 0; t < PJ + 7; ++t) {
            wl[t] = lq[(size_t)t * NCH];               // immediate offsets
            const float h = hq[(size_t)t * NCH];
            const float a = fabsf(h) - thr;
            wh[t] = (a > 0.f) ? copysignf(a, h) : 0.f;
        }
        float* __restrict__ op = out + ob + (size_t)(2 * j0) * NCH;
#pragma unroll
        for (int e = 0; e < PJ; ++e) {
            float a0 = 0.f, a1 = 0.f;
#pragma unroll
            for (int d = 0; d < 8; ++d) {
                a0 += wl[e + d] * DLO[2 * d + 1] + wh[e + d] * DHI[2 * d + 1];
                a1 += wl[e + d] * DLO[2 * d]     + wh[e + d] * DHI[2 * d];
            }
            op[(size_t)(2 * e) * NCH]     = a0;        // immediate offsets
            op[(size_t)(2 * e + 1) * NCH] = a1;
        }
    } else {
#pragma unroll
        for (int t = 0; t < PJ + 7; ++t) {
            int jj = j0 + t;
            if (jj > n - 1) jj = n - 1;  // clamped values feed only guarded-off outputs
            wl[t] = lob[(size_t)jj * NCH];
            const float h = hib[(size_t)jj * NCH];
            const float a = fabsf(h) - thr;
            wh[t] = (a > 0.f) ? copysignf(a, h) : 0.f;
        }
#pragma unroll
        for (int e = 0; e < PJ; ++e) {
            const int m = 2 * (j0 + e);
            if (m < nout) {
                float a0 = 0.f, a1 = 0.f;
#pragma unroll
                for (int d = 0; d < 8; ++d) {
                    a0 += wl[e + d] * DLO[2 * d + 1] + wh[e + d] * DHI[2 * d + 1];
                    a1 += wl[e + d] * DLO[2 * d]     + wh[e + d] * DHI[2 * d];
                }
                out[ob + (size_t)m * NCH] = a0;
                if (m + 1 < nout) out[ob + (size_t)(m + 1) * NCH] = a1;
            }
        }
    }
}

// ---- launch ----------------------------------------------------------------
// fwd1 -> { med || (fwd2 -> fwd3) } -> inv3 -> inv2 -> inv1 (med overlapped).
extern "C" void kernel_launch(void* const* d_in, const int* in_sizes, int n_in,
                              void* d_out, int out_size) {
    const float* x = (const float*)d_in[0];
    float* out = (float*)d_out;

    static cudaStream_t s2 = nullptr;
    static cudaEvent_t evF = nullptr, evJ = nullptr;
    if (s2 == nullptr) {
        cudaStreamCreateWithFlags(&s2, cudaStreamNonBlocking);
        cudaEventCreateWithFlags(&evF, cudaEventDisableTiming);
        cudaEventCreateWithFlags(&evJ, cudaEventDisableTiming);
    }

    const dim3 blk(128, 2);
    fwd_kernel<<<dim3(257, BATCH), blk>>>(x, 1);   // 4103

    cudaEventRecord(evF, 0);
    cudaStreamWaitEvent(s2, evF, 0);
    med_kernel<<<dim3(NCH / CPC, BATCH), 1024, 0, s2>>>();
    cudaEventRecord(evJ, s2);

    fwd_kernel<<<dim3(129, BATCH), blk>>>(x, 2);   // 2059
    fwd_kernel<<<dim3( 65, BATCH), blk>>>(x, 3);   // 1037

    cudaStreamWaitEvent(0, evJ, 0);
    inv_kernel<<<dim3( 65, BATCH), blk>>>(out, 3); // -> N2
    inv_kernel<<<dim3(129, BATCH), blk>>>(out, 2); // -> N1
    inv_kernel<<<dim3(256, BATCH), blk>>>(out, 1); // -> TLEN
}

// round 10
// speedup vs baseline: 2.8178x; 1.0400x over previous
#include <cuda_runtime.h>

#define BATCH 16
#define NCH   128
#define NC2   (NCH / 2)      // float2 channel pairs per row
#define TLEN  8192
#define N1    4103
#define N2    2059
#define N3    1037

// ---- scratch (static device arrays; no allocation) --------------------------
__device__ __align__(256) float g_lo1[BATCH * N1 * NCH];
__device__ __align__(256) float g_hi1[BATCH * N1 * NCH];
__device__ __align__(256) float g_lo2[BATCH * N2 * NCH];
__device__ __align__(256) float g_hi2[BATCH * N2 * NCH];
__device__ __align__(256) float g_lo3[BATCH * N3 * NCH];
__device__ __align__(256) float g_hi3[BATCH * N3 * NCH];
__device__ __align__(256) float g_thr[BATCH * NCH];

// ---- sym8 filters (compile-time literals -> imm-form FFMA) ------------------
#define FILT_RL {  0.0018899503327594609f, -0.0003029205147241331f, -0.01495225833704823f,   \
                   0.003808752013890615f,   0.049137179673607506f,  -0.027219029917056003f,  \
                  -0.05194583810770904f,    0.36444189483533895f,    0.7771857517005235f,    \
                   0.4813596512583722f,    -0.061273359067658524f,  -0.1432942383508097f,    \
                   0.007607487324917605f,   0.03169508781149298f,   -0.0005421323317911481f, \
                  -0.0033824159510061256f }
#define FILT_RH { -0.0033824159510061256f,  0.0005421323317911481f,  0.03169508781149298f,   \
                  -0.007607487324917605f,  -0.1432942383508097f,     0.061273359067658524f,  \
                   0.4813596512583722f,    -0.7771857517005235f,     0.36444189483533895f,   \
                   0.05194583810770904f,   -0.027219029917056003f,  -0.049137179673607506f,  \
                   0.003808752013890615f,   0.01495225833704823f,   -0.0003029205147241331f, \
                  -0.0018899503327594609f }
#define FILT_DLO { -0.0033824159510061256f, -0.0005421323317911481f,  0.03169508781149298f,  \
                    0.007607487324917605f,  -0.1432942383508097f,    -0.061273359067658524f, \
                    0.4813596512583722f,     0.7771857517005235f,     0.36444189483533895f,  \
                   -0.05194583810770904f,   -0.027219029917056003f,   0.049137179673607506f, \
                    0.003808752013890615f,  -0.01495225833704823f,   -0.0003029205147241331f,\
                    0.0018899503327594609f }
#define FILT_DHI { -0.0018899503327594609f, -0.0003029205147241331f,  0.01495225833704823f,  \
                    0.003808752013890615f,  -0.049137179673607506f,  -0.027219029917056003f, \
                    0.05194583810770904f,    0.36444189483533895f,   -0.7771857517005235f,   \
                    0.4813596512583722f,     0.061273359067658524f,  -0.1432942383508097f,   \
                   -0.007607487324917605f,   0.03169508781149298f,    0.0005421323317911481f,\
                   -0.0033824159510061256f }

// 0.85 / 0.6745 * sqrt(2*log(8192))
#define THRSCALE ((float)(0.85 * 4.2452122112874176 / 0.6745))

#define WLO   0.55f
#define WHI   0.80f
#define MBINS 128
#define MCAP  32
#define KRANK 2051   // 0-based lower-median rank of 4103

#define PF 8
#define PJ 8

// ---- forward analysis: float2 over channel pairs, stride-2 16-tap ----------
__global__ __launch_bounds__(256) void fwd_kernel(const float* __restrict__ x0, int level) {
    const float* __restrict__ in;
    float* __restrict__ lo;
    float* __restrict__ hi;
    int nin, nout;
    if (level == 1)      { in = x0;    lo = g_lo1; hi = g_hi1; nin = TLEN; nout = N1; }
    else if (level == 2) { in = g_lo1; lo = g_lo2; hi = g_hi2; nin = N1;   nout = N2; }
    else                 { in = g_lo2; lo = g_lo3; hi = g_hi3; nin = N2;   nout = N3; }

    const int b  = blockIdx.y;
    const int nn = threadIdx.x;                         // channel pair 0..63
    const int p0 = (blockIdx.x * blockDim.y + threadIdx.y) * PF;
    if (p0 >= nout) return;

    const float RL[16] = FILT_RL;
    const float RH[16] = FILT_RH;

    const float2* __restrict__ inb = reinterpret_cast<const float2*>(in)
                                     + (size_t)(b * nin) * NC2 + nn;
    float2* __restrict__ lo2p = reinterpret_cast<float2*>(lo)
                                + (size_t)(b * nout + p0) * NC2 + nn;
    float2* __restrict__ hi2p = reinterpret_cast<float2*>(hi)
                                + (size_t)(b * nout + p0) * NC2 + nn;

    float2 w[2 * PF + 14];
    const bool interior = (p0 >= 7) && (2 * p0 + 15 < nin) && (p0 + PF <= nout);

    if (interior) {
        const float2* __restrict__ q = inb + (size_t)(2 * p0 - 14) * NC2;
#pragma unroll
        for (int t = 0; t < 2 * PF + 14; ++t)
            w[t] = q[(size_t)t * NC2];                  // immediate offsets
#pragma unroll
        for (int e = 0; e < PF; ++e) {
            float2 alo = {0.f, 0.f}, ahi = {0.f, 0.f};
#pragma unroll
            for (int k = 0; k < 16; ++k) {
                const float2 v = w[2 * e + k];
                alo.x += v.x * RL[k];  alo.y += v.y * RL[k];
                ahi.x += v.x * RH[k];  ahi.y += v.y * RH[k];
            }
            lo2p[(size_t)e * NC2] = alo;
            hi2p[(size_t)e * NC2] = ahi;
        }
    } else {
#pragma unroll
        for (int t = 0; t < 2 * PF + 14; ++t) {
            int i = 2 * p0 - 14 + t;
            if (i < 0)    i = -1 - i;
            if (i >= nin) i = 2 * nin - 1 - i;
            w[t] = inb[(size_t)i * NC2];
        }
#pragma unroll
        for (int e = 0; e < PF; ++e) {
            if (p0 + e < nout) {
                float2 alo = {0.f, 0.f}, ahi = {0.f, 0.f};
#pragma unroll
                for (int k = 0; k < 16; ++k) {
                    const float2 v = w[2 * e + k];
                    alo.x += v.x * RL[k];  alo.y += v.y * RL[k];
                    ahi.x += v.x * RH[k];  ahi.y += v.y * RH[k];
                }
                lo2p[(size_t)e * NC2] = alo;
                hi2p[(size_t)e * NC2] = ahi;
            }
        }
    }
}

// ---- median of |cd1|: histogram-window selection, 8 channels/CTA ------------
#define CPC   8
#define HPAD  9
__global__ __launch_bounds__(1024) void med_kernel() {
    __shared__ unsigned int s_hist[MBINS * HPAD];
    __shared__ unsigned int s_below[CPC];
    __shared__ unsigned int s_cand[MCAP * CPC];
    __shared__ unsigned int s_cnt[CPC];
    __shared__ int s_tbin[CPC];
    __shared__ int s_krem[CPC];
    __shared__ unsigned int s_fb;
    __shared__ int s_red;

    const int tid   = threadIdx.x;
    const int lane  = tid & 31;
    const int ch    = tid & (CPC - 1);
    const int slice = tid >> 3;
    const int b     = blockIdx.y;
    const int n0    = blockIdx.x * CPC;
    const float* __restrict__ base = g_hi1 + (size_t)(b * N1) * NCH + n0 + ch;

    for (int i = tid; i < MBINS * HPAD; i += 1024) s_hist[i] = 0u;
    if (tid < CPC) { s_below[tid] = 0u; s_cnt[tid] = 0u; }
    if (tid == 0) s_fb = 0u;
    __syncthreads();

    int below = 0;
#pragma unroll 1
    for (int it = 0; it < 4; ++it) {
        float v[8];
#pragma unroll
        for (int q = 0; q < 8; ++q) {
            const int p = slice + 128 * (it * 8 + q);
            v[q] = fabsf(__ldg(base + (size_t)p * NCH));
        }
#pragma unroll
        for (int q = 0; q < 8; ++q) {
            below += (v[q] < WLO) ? 1 : 0;
            if (v[q] >= WLO && v[q] < WHI) {
                int bin = (int)((v[q] - WLO) * 512.0f);
                bin = bin > (MBINS - 1) ? (MBINS - 1) : bin;
                atomicAdd(&s_hist[bin * HPAD + ch], 1u);
            }
        }
    }
    {
        const int p = slice + 4096;
        if (p < N1) {
            const float v = fabsf(__ldg(base + (size_t)p * NCH));
            below += (v < WLO) ? 1 : 0;
            if (v >= WLO && v < WHI) {
                int bin = (int)((v - WLO) * 512.0f);
                bin = bin > (MBINS - 1) ? (MBINS - 1) : bin;
                atomicAdd(&s_hist[bin * HPAD + ch], 1u);
            }
        }
    }
    below += __shfl_down_sync(0xffffffffu, below, 16);
    below += __shfl_down_sync(0xffffffffu, below, 8);
    if (lane < CPC) atomicAdd(&s_below[lane], (unsigned int)below);
    __syncthreads();

    if (tid < CPC) {
        int rr = KRANK - (int)s_below[tid];
        int t = -1;
        if (rr >= 0) {
            for (int bn = 0; bn < MBINS; ++bn) {
                const int c = (int)s_hist[bn * HPAD + tid];
                if (rr < c) { t = bn; break; }
                rr -= c;
            }
        }
        s_tbin[tid] = t;
        s_krem[tid] = rr;
        if (t < 0) atomicOr(&s_fb, 1u << tid);
    }
    __syncthreads();

    const int tb = s_tbin[ch];
#pragma unroll 1
    for (int it = 0; it < 4; ++it) {
        float v[8];
#pragma unroll
        for (int q = 0; q < 8; ++q) {
            const int p = slice + 128 * (it * 8 + q);
            v[q] = fabsf(__ldg(base + (size_t)p * NCH));
        }
#pragma unroll
        for (int q = 0; q < 8; ++q) {
            if (v[q] >= WLO && v[q] < WHI) {
                int bin = (int)((v[q] - WLO) * 512.0f);
                bin = bin > (MBINS - 1) ? (MBINS - 1) : bin;
                if (bin == tb) {
                    const unsigned int idx = atomicAdd(&s_cnt[ch], 1u);
                    if (idx < MCAP) s_cand[idx * CPC + ch] = __float_as_uint(v[q]);
                }
            }
        }
    }
    {
        const int p = slice + 4096;
        if (p < N1) {
            const float v = fabsf(__ldg(base + (size_t)p * NCH));
            if (v >= WLO && v < WHI) {
                int bin = (int)((v - WLO) * 512.0f);
                bin = bin > (MBINS - 1) ? (MBINS - 1) : bin;
                if (bin == tb) {
                    const unsigned int idx = atomicAdd(&s_cnt[ch], 1u);
                    if (idx < MCAP) s_cand[idx * CPC + ch] = __float_as_uint(v);
                }
            }
        }
    }
    __syncthreads();

    if (tid < CPC && s_cnt[tid] > MCAP) atomicOr(&s_fb, 1u << tid);
    __syncthreads();
    const unsigned int fb = s_fb;

    if (tid < CPC && !((fb >> tid) & 1u)) {
        const int c = (int)s_cnt[tid];
        const int k = s_krem[tid];
        unsigned int res = 0u;
        for (int i = 0; i < c; ++i) {
            const unsigned int x = s_cand[i * CPC + tid];
            int lt = 0, le = 0;
            for (int jj = 0; jj < c; ++jj) {
                const unsigned int y = s_cand[jj * CPC + tid];
                lt += (y < x);
                le += (y <= x);
            }
            if (lt <= k && k < le) res = x;
        }
        g_thr[b * NCH + n0 + tid] = __uint_as_float(res) * THRSCALE;
    }
    __syncthreads();

    if (fb) {
        for (int c2 = 0; c2 < CPC; ++c2) {
            if (!((fb >> c2) & 1u)) continue;
            const float* __restrict__ bp = g_hi1 + (size_t)(b * N1) * NCH + n0 + c2;
            unsigned int prefix = 0u;
            int kk = KRANK;
            for (int bit = 31; bit >= 0; --bit) {
                if (tid == 0) s_red = 0;
                __syncthreads();
                const unsigned int hi = prefix >> bit;
                int local = 0;
                for (int p = tid; p < N1; p += 1024) {
                    const unsigned int e = __float_as_uint(fabsf(bp[(size_t)p * NCH]));
                    if ((e >> bit) == hi) local++;
                }
                atomicAdd(&s_red, local);
                __syncthreads();
                const int c0 = s_red;
                if (kk >= c0) { kk -= c0; prefix |= (1u << bit); }
                __syncthreads();
            }
            if (tid == 0) g_thr[b * NCH + n0 + c2] = __uint_as_float(prefix) * THRSCALE;
        }
    }
}

// ---- inverse synthesis: float2 over channel pairs, threshold fused ---------
__global__ __launch_bounds__(256) void inv_kernel(float* __restrict__ dout, int level) {
    const float* __restrict__ lo;
    const float* __restrict__ hi;
    float* __restrict__ out;
    int n, nout;
    if (level == 3)      { lo = g_lo3; hi = g_hi3; out = g_lo2; n = N3; nout = N2;   }
    else if (level == 2) { lo = g_lo2; hi = g_hi2; out = g_lo1; n = N2; nout = N1;   }
    else                 { lo = g_lo1; hi = g_hi1; out = dout;  n = N1; nout = TLEN; }

    const int b  = blockIdx.y;
    const int nn = threadIdx.x;                         // channel pair 0..63
    const int j0 = (blockIdx.x * blockDim.y + threadIdx.y) * PJ;
    if (2 * j0 >= nout) return;

    const float2 thr = reinterpret_cast<const float2*>(g_thr)[b * NC2 + nn];
    const float DLO[16] = FILT_DLO;
    const float DHI[16] = FILT_DHI;

    const float2* __restrict__ lob = reinterpret_cast<const float2*>(lo)
                                     + (size_t)(b * n) * NC2 + nn;
    const float2* __restrict__ hib = reinterpret_cast<const float2*>(hi)
                                     + (size_t)(b * n) * NC2 + nn;
    float2* __restrict__ ob = reinterpret_cast<float2*>(out)
                              + (size_t)(b * nout) * NC2 + nn;

    float2 wl[PJ + 7], wh[PJ + 7];
    const bool interior = (j0 + PJ + 6 < n) && (2 * (j0 + PJ) <= nout);

    if (interior) {
        const float2* __restrict__ lq = lob + (size_t)j0 * NC2;
        const float2* __restrict__ hq = hib + (size_t)j0 * NC2;
#pragma unroll
        for (int t = 0; t < PJ + 7; ++t) {
            wl[t] = lq[(size_t)t * NC2];
            const float2 h = hq[(size_t)t * NC2];
            const float ax = fabsf(h.x) - thr.x;
            const float ay = fabsf(h.y) - thr.y;
            wh[t].x = (ax > 0.f) ? copysignf(ax, h.x) : 0.f;
            wh[t].y = (ay > 0.f) ? copysignf(ay, h.y) : 0.f;
        }
        float2* __restrict__ op = ob + (size_t)(2 * j0) * NC2;
#pragma unroll
        for (int e = 0; e < PJ; ++e) {
            float2 a0 = {0.f, 0.f}, a1 = {0.f, 0.f};
#pragma unroll
            for (int d = 0; d < 8; ++d) {
                const float2 l = wl[e + d], h = wh[e + d];
                a0.x += l.x * DLO[2 * d + 1] + h.x * DHI[2 * d + 1];
                a0.y += l.y * DLO[2 * d + 1] + h.y * DHI[2 * d + 1];
                a1.x += l.x * DLO[2 * d]     + h.x * DHI[2 * d];
                a1.y += l.y * DLO[2 * d]     + h.y * DHI[2 * d];
            }
            op[(size_t)(2 * e) * NC2]     = a0;
            op[(size_t)(2 * e + 1) * NC2] = a1;
        }
    } else {
#pragma unroll
        for (int t = 0; t < PJ + 7; ++t) {
            int jj = j0 + t;
            if (jj > n - 1) jj = n - 1;  // clamped values feed only guarded-off outputs
            wl[t] = lob[(size_t)jj * NC2];
            const float2 h = hib[(size_t)jj * NC2];
            const float ax = fabsf(h.x) - thr.x;
            const float ay = fabsf(h.y) - thr.y;
            wh[t].x = (ax > 0.f) ? copysignf(ax, h.x) : 0.f;
            wh[t].y = (ay > 0.f) ? copysignf(ay, h.y) : 0.f;
        }
#pragma unroll
        for (int e = 0; e < PJ; ++e) {
            const int m = 2 * (j0 + e);
            if (m < nout) {
                float2 a0 = {0.f, 0.f}, a1 = {0.f, 0.f};
#pragma unroll
                for (int d = 0; d < 8; ++d) {
                    const float2 l = wl[e + d], h = wh[e + d];
                    a0.x += l.x * DLO[2 * d + 1] + h.x * DHI[2 * d + 1];
                    a0.y += l.y * DLO[2 * d + 1] + h.y * DHI[2 * d + 1];
                    a1.x += l.x * DLO[2 * d]     + h.x * DHI[2 * d];
                    a1.y += l.y * DLO[2 * d]     + h.y * DHI[2 * d];
                }
                ob[(size_t)m * NC2] = a0;
                if (m + 1 < nout) ob[(size_t)(m + 1) * NC2] = a1;
            }
        }
    }
}

// ---- launch ----------------------------------------------------------------
// fwd1 -> { med || (fwd2 -> fwd3) } -> inv3 -> inv2 -> inv1 (med overlapped).
extern "C" void kernel_launch(void* const* d_in, const int* in_sizes, int n_in,
                              void* d_out, int out_size) {
    const float* x = (const float*)d_in[0];
    float* out = (float*)d_out;

    static cudaStream_t s2 = nullptr;
    static cudaEvent_t evF = nullptr, evJ = nullptr;
    if (s2 == nullptr) {
        cudaStreamCreateWithFlags(&s2, cudaStreamNonBlocking);
        cudaEventCreateWithFlags(&evF, cudaEventDisableTiming);
        cudaEventCreateWithFlags(&evJ, cudaEventDisableTiming);
    }

    const dim3 blk(64, 4);   // 64 channel pairs x 4 p-tiles
    fwd_kernel<<<dim3(129, BATCH), blk>>>(x, 1);   // ceil(4103/32)

    cudaEventRecord(evF, 0);
    cudaStreamWaitEvent(s2, evF, 0);
    med_kernel<<<dim3(NCH / CPC, BATCH), 1024, 0, s2>>>();
    cudaEventRecord(evJ, s2);

    fwd_kernel<<<dim3( 65, BATCH), blk>>>(x, 2);   // ceil(2059/32)
    fwd_kernel<<<dim3( 33, BATCH), blk>>>(x, 3);   // ceil(1037/32)

    cudaStreamWaitEvent(0, evJ, 0);
    inv_kernel<<<dim3( 33, BATCH), blk>>>(out, 3); // ceil(1030/32)
    inv_kernel<<<dim3( 65, BATCH), blk>>>(out, 2); // ceil(2052/32)
    inv_kernel<<<dim3(128, BATCH), blk>>>(out, 1); // 4096/32
}

// round 13
// speedup vs baseline: 2.9153x; 1.0346x over previous
#include <cuda_runtime.h>

#define BATCH 16
#define BPC   8              // batches per chunk (2 chunks, 2 streams)
#define NCH   128
#define NC2   (NCH / 2)
#define TLEN  8192
#define N1    4103
#define N2    2059
#define N3    1037

// ---- scratch (static device arrays; no allocation) --------------------------
__device__ __align__(256) float g_lo1[BATCH * N1 * NCH];
__device__ __align__(256) float g_hi1[BATCH * N1 * NCH];
__device__ __align__(256) float g_lo2[BATCH * N2 * NCH];
__device__ __align__(256) float g_hi2[BATCH * N2 * NCH];
__device__ __align__(256) float g_lo3[BATCH * N3 * NCH];
__device__ __align__(256) float g_hi3[BATCH * N3 * NCH];
__device__ __align__(256) float g_thr[BATCH * NCH];

// ---- sym8 filters (compile-time literals -> imm-form FFMA) ------------------
#define FILT_RL {  0.0018899503327594609f, -0.0003029205147241331f, -0.01495225833704823f,   \
                   0.003808752013890615f,   0.049137179673607506f,  -0.027219029917056003f,  \
                  -0.05194583810770904f,    0.36444189483533895f,    0.7771857517005235f,    \
                   0.4813596512583722f,    -0.061273359067658524f,  -0.1432942383508097f,    \
                   0.007607487324917605f,   0.03169508781149298f,   -0.0005421323317911481f, \
                  -0.0033824159510061256f }
#define FILT_RH { -0.0033824159510061256f,  0.0005421323317911481f,  0.03169508781149298f,   \
                  -0.007607487324917605f,  -0.1432942383508097f,     0.061273359067658524f,  \
                   0.4813596512583722f,    -0.7771857517005235f,     0.36444189483533895f,   \
                   0.05194583810770904f,   -0.027219029917056003f,  -0.049137179673607506f,  \
                   0.003808752013890615f,   0.01495225833704823f,   -0.0003029205147241331f, \
                  -0.0018899503327594609f }
#define FILT_DLO { -0.0033824159510061256f, -0.0005421323317911481f,  0.03169508781149298f,  \
                    0.007607487324917605f,  -0.1432942383508097f,    -0.061273359067658524f, \
                    0.4813596512583722f,     0.7771857517005235f,     0.36444189483533895f,  \
                   -0.05194583810770904f,   -0.027219029917056003f,   0.049137179673607506f, \
                    0.003808752013890615f,  -0.01495225833704823f,   -0.0003029205147241331f,\
                    0.0018899503327594609f }
#define FILT_DHI { -0.0018899503327594609f, -0.0003029205147241331f,  0.01495225833704823f,  \
                    0.003808752013890615f,  -0.049137179673607506f,  -0.027219029917056003f, \
                    0.05194583810770904f,    0.36444189483533895f,   -0.7771857517005235f,   \
                    0.4813596512583722f,     0.061273359067658524f,  -0.1432942383508097f,   \
                   -0.007607487324917605f,   0.03169508781149298f,    0.0005421323317911481f,\
                   -0.0033824159510061256f }

// 0.85 / 0.6745 * sqrt(2*log(8192))
#define THRSCALE ((float)(0.85 * 4.2452122112874176 / 0.6745))

#define WLO   0.55f
#define WHI   0.80f
#define MBINS 128
#define MCAP  32
#define KRANK 2051

#define PF 8
#define PJ 8

// ---- forward analysis: float2 over channel pairs, stride-2 16-tap ----------
__global__ __launch_bounds__(256) void fwd_kernel(const float* __restrict__ x0,
                                                  int level, int b0) {
    const float* __restrict__ in;
    float* __restrict__ lo;
    float* __restrict__ hi;
    int nin, nout;
    if (level == 1)      { in = x0;    lo = g_lo1; hi = g_hi1; nin = TLEN; nout = N1; }
    else if (level == 2) { in = g_lo1; lo = g_lo2; hi = g_hi2; nin = N1;   nout = N2; }
    else                 { in = g_lo2; lo = g_lo3; hi = g_hi3; nin = N2;   nout = N3; }

    const int b  = b0 + blockIdx.y;
    const int nn = threadIdx.x;
    const int p0 = (blockIdx.x * blockDim.y + threadIdx.y) * PF;
    if (p0 >= nout) return;

    const float RL[16] = FILT_RL;
    const float RH[16] = FILT_RH;

    const float2* __restrict__ inb = reinterpret_cast<const float2*>(in)
                                     + (size_t)(b * nin) * NC2 + nn;
    float2* __restrict__ lo2p = reinterpret_cast<float2*>(lo)
                                + (size_t)(b * nout + p0) * NC2 + nn;
    float2* __restrict__ hi2p = reinterpret_cast<float2*>(hi)
                                + (size_t)(b * nout + p0) * NC2 + nn;

    float2 w[2 * PF + 14];
    const bool interior = (p0 >= 7) && (2 * p0 + 15 < nin) && (p0 + PF <= nout);

    if (interior) {
        const float2* __restrict__ q = inb + (size_t)(2 * p0 - 14) * NC2;
#pragma unroll
        for (int t = 0; t < 2 * PF + 14; ++t)
            w[t] = q[(size_t)t * NC2];
#pragma unroll
        for (int e = 0; e < PF; ++e) {
            float2 alo = {0.f, 0.f}, ahi = {0.f, 0.f};
#pragma unroll
            for (int k = 0; k < 16; ++k) {
                const float2 v = w[2 * e + k];
                alo.x += v.x * RL[k];  alo.y += v.y * RL[k];
                ahi.x += v.x * RH[k];  ahi.y += v.y * RH[k];
            }
            lo2p[(size_t)e * NC2] = alo;
            hi2p[(size_t)e * NC2] = ahi;
        }
    } else {
#pragma unroll
        for (int t = 0; t < 2 * PF + 14; ++t) {
            int i = 2 * p0 - 14 + t;
            if (i < 0)    i = -1 - i;
            if (i >= nin) i = 2 * nin - 1 - i;
            w[t] = inb[(size_t)i * NC2];
        }
#pragma unroll
        for (int e = 0; e < PF; ++e) {
            if (p0 + e < nout) {
                float2 alo = {0.f, 0.f}, ahi = {0.f, 0.f};
#pragma unroll
                for (int k = 0; k < 16; ++k) {
                    const float2 v = w[2 * e + k];
                    alo.x += v.x * RL[k];  alo.y += v.y * RL[k];
                    ahi.x += v.x * RH[k];  ahi.y += v.y * RH[k];
                }
                lo2p[(size_t)e * NC2] = alo;
                hi2p[(size_t)e * NC2] = ahi;
            }
        }
    }
}

// ---- median of |cd1|: histogram-window selection, 8 channels/CTA ------------
#define CPC   8
#define HPAD  9
__global__ __launch_bounds__(1024) void med_kernel(int b0) {
    __shared__ unsigned int s_hist[MBINS * HPAD];
    __shared__ unsigned int s_below[CPC];
    __shared__ unsigned int s_cand[MCAP * CPC];
    __shared__ unsigned int s_cnt[CPC];
    __shared__ int s_tbin[CPC];
    __shared__ int s_krem[CPC];
    __shared__ unsigned int s_fb;
    __shared__ int s_red;

    const int tid   = threadIdx.x;
    const int lane  = tid & 31;
    const int ch    = tid & (CPC - 1);
    const int slice = tid >> 3;
    const int b     = b0 + blockIdx.y;
    const int n0    = blockIdx.x * CPC;
    const float* __restrict__ base = g_hi1 + (size_t)(b * N1) * NCH + n0 + ch;

    for (int i = tid; i < MBINS * HPAD; i += 1024) s_hist[i] = 0u;
    if (tid < CPC) { s_below[tid] = 0u; s_cnt[tid] = 0u; }
    if (tid == 0) s_fb = 0u;
    __syncthreads();

    int below = 0;
#pragma unroll 1
    for (int it = 0; it < 4; ++it) {
        float v[8];
#pragma unroll
        for (int q = 0; q < 8; ++q) {
            const int p = slice + 128 * (it * 8 + q);
            v[q] = fabsf(__ldg(base + (size_t)p * NCH));
        }
#pragma unroll
        for (int q = 0; q < 8; ++q) {
            below += (v[q] < WLO) ? 1 : 0;
            if (v[q] >= WLO && v[q] < WHI) {
                int bin = (int)((v[q] - WLO) * 512.0f);
                bin = bin > (MBINS - 1) ? (MBINS - 1) : bin;
                atomicAdd(&s_hist[bin * HPAD + ch], 1u);
            }
        }
    }
    {
        const int p = slice + 4096;
        if (p < N1) {
            const float v = fabsf(__ldg(base + (size_t)p * NCH));
            below += (v < WLO) ? 1 : 0;
            if (v >= WLO && v < WHI) {
                int bin = (int)((v - WLO) * 512.0f);
                bin = bin > (MBINS - 1) ? (MBINS - 1) : bin;
                atomicAdd(&s_hist[bin * HPAD + ch], 1u);
            }
        }
    }
    below += __shfl_down_sync(0xffffffffu, below, 16);
    below += __shfl_down_sync(0xffffffffu, below, 8);
    if (lane < CPC) atomicAdd(&s_below[lane], (unsigned int)below);
    __syncthreads();

    if (tid < CPC) {
        int rr = KRANK - (int)s_below[tid];
        int t = -1;
        if (rr >= 0) {
            for (int bn = 0; bn < MBINS; ++bn) {
                const int c = (int)s_hist[bn * HPAD + tid];
                if (rr < c) { t = bn; break; }
                rr -= c;
            }
        }
        s_tbin[tid] = t;
        s_krem[tid] = rr;
        if (t < 0) atomicOr(&s_fb, 1u << tid);
    }
    __syncthreads();

    const int tb = s_tbin[ch];
#pragma unroll 1
    for (int it = 0; it < 4; ++it) {
        float v[8];
#pragma unroll
        for (int q = 0; q < 8; ++q) {
            const int p = slice + 128 * (it * 8 + q);
            v[q] = fabsf(__ldg(base + (size_t)p * NCH));
        }
#pragma unroll
        for (int q = 0; q < 8; ++q) {
            if (v[q] >= WLO && v[q] < WHI) {
                int bin = (int)((v[q] - WLO) * 512.0f);
                bin = bin > (MBINS - 1) ? (MBINS - 1) : bin;
                if (bin == tb) {
                    const unsigned int idx = atomicAdd(&s_cnt[ch], 1u);
                    if (idx < MCAP) s_cand[idx * CPC + ch] = __float_as_uint(v[q]);
                }
            }
        }
    }
    {
        const int p = slice + 4096;
        if (p < N1) {
            const float v = fabsf(__ldg(base + (size_t)p * NCH));
            if (v >= WLO && v < WHI) {
                int bin = (int)((v - WLO) * 512.0f);
                bin = bin > (MBINS - 1) ? (MBINS - 1) : bin;
                if (bin == tb) {
                    const unsigned int idx = atomicAdd(&s_cnt[ch], 1u);
                    if (idx < MCAP) s_cand[idx * CPC + ch] = __float_as_uint(v);
                }
            }
        }
    }
    __syncthreads();

    if (tid < CPC && s_cnt[tid] > MCAP) atomicOr(&s_fb, 1u << tid);
    __syncthreads();
    const unsigned int fb = s_fb;

    if (tid < CPC && !((fb >> tid) & 1u)) {
        const int c = (int)s_cnt[tid];
        const int k = s_krem[tid];
        unsigned int res = 0u;
        for (int i = 0; i < c; ++i) {
            const unsigned int x = s_cand[i * CPC + tid];
            int lt = 0, le = 0;
            for (int jj = 0; jj < c; ++jj) {
                const unsigned int y = s_cand[jj * CPC + tid];
                lt += (y < x);
                le += (y <= x);
            }
            if (lt <= k && k < le) res = x;
        }
        g_thr[b * NCH + n0 + tid] = __uint_as_float(res) * THRSCALE;
    }
    __syncthreads();

    if (fb) {
        for (int c2 = 0; c2 < CPC; ++c2) {
            if (!((fb >> c2) & 1u)) continue;
            const float* __restrict__ bp = g_hi1 + (size_t)(b * N1) * NCH + n0 + c2;
            unsigned int prefix = 0u;
            int kk = KRANK;
            for (int bit = 31; bit >= 0; --bit) {
                if (tid == 0) s_red = 0;
                __syncthreads();
                const unsigned int hi = prefix >> bit;
                int local = 0;
                for (int p = tid; p < N1; p += 1024) {
                    const unsigned int e = __float_as_uint(fabsf(bp[(size_t)p * NCH]));
                    if ((e >> bit) == hi) local++;
                }
                atomicAdd(&s_red, local);
                __syncthreads();
                const int c0 = s_red;
                if (kk >= c0) { kk -= c0; prefix |= (1u << bit); }
                __syncthreads();
            }
            if (tid == 0) g_thr[b * NCH + n0 + c2] = __uint_as_float(prefix) * THRSCALE;
        }
    }
}

// ---- inverse synthesis: float2 over channel pairs, threshold fused ---------
__global__ __launch_bounds__(256) void inv_kernel(float* __restrict__ dout,
                                                  int level, int b0) {
    const float* __restrict__ lo;
    const float* __restrict__ hi;
    float* __restrict__ out;
    int n, nout;
    if (level == 3)      { lo = g_lo3; hi = g_hi3; out = g_lo2; n = N3; nout = N2;   }
    else if (level == 2) { lo = g_lo2; hi = g_hi2; out = g_lo1; n = N2; nout = N1;   }
    else                 { lo = g_lo1; hi = g_hi1; out = dout;  n = N1; nout = TLEN; }

    const int b  = b0 + blockIdx.y;
    const int nn = threadIdx.x;
    const int j0 = (blockIdx.x * blockDim.y + threadIdx.y) * PJ;
    if (2 * j0 >= nout) return;

    const float2 thr = reinterpret_cast<const float2*>(g_thr)[b * NC2 + nn];
    const float DLO[16] = FILT_DLO;
    const float DHI[16] = FILT_DHI;

    const float2* __restrict__ lob = reinterpret_cast<const float2*>(lo)
                                     + (size_t)(b * n) * NC2 + nn;
    const float2* __restrict__ hib = reinterpret_cast<const float2*>(hi)
                                     + (size_t)(b * n) * NC2 + nn;
    float2* __restrict__ ob = reinterpret_cast<float2*>(out)
                              + (size_t)(b * nout) * NC2 + nn;

    float2 wl[PJ + 7], wh[PJ + 7];
    const bool interior = (j0 + PJ + 6 < n) && (2 * (j0 + PJ) <= nout);

    if (interior) {
        const float2* __restrict__ lq = lob + (size_t)j0 * NC2;
        const float2* __restrict__ hq = hib + (size_t)j0 * NC2;
#pragma unroll
        for (int t = 0; t < PJ + 7; ++t) {
            wl[t] = lq[(size_t)t * NC2];
            const float2 h = hq[(size_t)t * NC2];
            const float ax = fabsf(h.x) - thr.x;
            const float ay = fabsf(h.y) - thr.y;
            wh[t].x = (ax > 0.f) ? copysignf(ax, h.x) : 0.f;
            wh[t].y = (ay > 0.f) ? copysignf(ay, h.y) : 0.f;
        }
        float2* __restrict__ op = ob + (size_t)(2 * j0) * NC2;
#pragma unroll
        for (int e = 0; e < PJ; ++e) {
            float2 a0 = {0.f, 0.f}, a1 = {0.f, 0.f};
#pragma unroll
            for (int d = 0; d < 8; ++d) {
                const float2 l = wl[e + d], h = wh[e + d];
                a0.x += l.x * DLO[2 * d + 1] + h.x * DHI[2 * d + 1];
                a0.y += l.y * DLO[2 * d + 1] + h.y * DHI[2 * d + 1];
                a1.x += l.x * DLO[2 * d]     + h.x * DHI[2 * d];
                a1.y += l.y * DLO[2 * d]     + h.y * DHI[2 * d];
            }
            op[(size_t)(2 * e) * NC2]     = a0;
            op[(size_t)(2 * e + 1) * NC2] = a1;
        }
    } else {
#pragma unroll
        for (int t = 0; t < PJ + 7; ++t) {
            int jj = j0 + t;
            if (jj > n - 1) jj = n - 1;
            wl[t] = lob[(size_t)jj * NC2];
            const float2 h = hib[(size_t)jj * NC2];
            const float ax = fabsf(h.x) - thr.x;
            const float ay = fabsf(h.y) - thr.y;
            wh[t].x = (ax > 0.f) ? copysignf(ax, h.x) : 0.f;
            wh[t].y = (ay > 0.f) ? copysignf(ay, h.y) : 0.f;
        }
#pragma unroll
        for (int e = 0; e < PJ; ++e) {
            const int m = 2 * (j0 + e);
            if (m < nout) {
                float2 a0 = {0.f, 0.f}, a1 = {0.f, 0.f};
#pragma unroll
                for (int d = 0; d < 8; ++d) {
                    const float2 l = wl[e + d], h = wh[e + d];
                    a0.x += l.x * DLO[2 * d + 1] + h.x * DHI[2 * d + 1];
                    a0.y += l.y * DLO[2 * d + 1] + h.y * DHI[2 * d + 1];
                    a1.x += l.x * DLO[2 * d]     + h.x * DHI[2 * d];
                    a1.y += l.y * DLO[2 * d]     + h.y * DHI[2 * d];
                }
                ob[(size_t)m * NC2] = a0;
                if (m + 1 < nout) ob[(size_t)(m + 1) * NC2] = a1;
            }
        }
    }
}

// ---- launch: two batch-chunk chains on two streams (proven footprint) -------
// chunk0 (b 0..7) on capture-origin stream; chunk1 (b 8..15) on s2.
// Each chain: fwd1 -> fwd2 -> fwd3 -> med -> inv3 -> inv2 -> inv1.
// Cross-chunk concurrency fills wave tails, launch gaps, and med exposure.
extern "C" void kernel_launch(void* const* d_in, const int* in_sizes, int n_in,
                              void* d_out, int out_size) {
    const float* x = (const float*)d_in[0];
    float* out = (float*)d_out;

    static cudaStream_t s2 = nullptr;
    static cudaEvent_t evF = nullptr, evJ = nullptr;
    if (s2 == nullptr) {
        cudaStreamCreateWithFlags(&s2, cudaStreamNonBlocking);
        cudaEventCreateWithFlags(&evF, cudaEventDisableTiming);
        cudaEventCreateWithFlags(&evJ, cudaEventDisableTiming);
    }

    const dim3 blk(64, 4);   // 64 channel pairs x 4 p-tiles

    cudaEventRecord(evF, 0);
    cudaStreamWaitEvent(s2, evF, 0);

    // chunk 1 on s2 (issue first so it starts immediately)
    fwd_kernel<<<dim3(129, BPC), blk, 0, s2>>>(x, 1, BPC);
    fwd_kernel<<<dim3( 65, BPC), blk, 0, s2>>>(x, 2, BPC);
    fwd_kernel<<<dim3( 33, BPC), blk, 0, s2>>>(x, 3, BPC);
    med_kernel<<<dim3(NCH / CPC, BPC), 1024, 0, s2>>>(BPC);
    inv_kernel<<<dim3( 33, BPC), blk, 0, s2>>>(out, 3, BPC);
    inv_kernel<<<dim3( 65, BPC), blk, 0, s2>>>(out, 2, BPC);
    inv_kernel<<<dim3(128, BPC), blk, 0, s2>>>(out, 1, BPC);
    cudaEventRecord(evJ, s2);

    // chunk 0 on the capture-origin stream
    fwd_kernel<<<dim3(129, BPC), blk>>>(x, 1, 0);
    fwd_kernel<<<dim3( 65, BPC), blk>>>(x, 2, 0);
    fwd_kernel<<<dim3( 33, BPC), blk>>>(x, 3, 0);
    med_kernel<<<dim3(NCH / CPC, BPC), 1024>>>(0);
    inv_kernel<<<dim3( 33, BPC), blk>>>(out, 3, 0);
    inv_kernel<<<dim3( 65, BPC), blk>>>(out, 2, 0);
    inv_kernel<<<dim3(128, BPC), blk>>>(out, 1, 0);

    cudaStreamWaitEvent(0, evJ, 0);
}

// round 14
// speedup vs baseline: 2.9352x; 1.0068x over previous
#include <cuda_runtime.h>

#define BATCH 16
#define BPC   8              // batches per chunk (2 chunks, 2 streams)
#define NCH   128
#define NC2   (NCH / 2)
#define TLEN  8192
#define N1    4103
#define N2    2059
#define N3    1037

// ---- scratch (static device arrays; no allocation) --------------------------
__device__ __align__(256) float g_lo1[BATCH * N1 * NCH];
__device__ __align__(256) float g_hi1[BATCH * N1 * NCH];
__device__ __align__(256) float g_lo2[BATCH * N2 * NCH];
__device__ __align__(256) float g_hi2[BATCH * N2 * NCH];
__device__ __align__(256) float g_lo3[BATCH * N3 * NCH];
__device__ __align__(256) float g_hi3[BATCH * N3 * NCH];
__device__ __align__(256) float g_thr[BATCH * NCH];

// ---- sym8 filters (compile-time literals -> imm-form FFMA) ------------------
#define FILT_RL {  0.0018899503327594609f, -0.0003029205147241331f, -0.01495225833704823f,   \
                   0.003808752013890615f,   0.049137179673607506f,  -0.027219029917056003f,  \
                  -0.05194583810770904f,    0.36444189483533895f,    0.7771857517005235f,    \
                   0.4813596512583722f,    -0.061273359067658524f,  -0.1432942383508097f,    \
                   0.007607487324917605f,   0.03169508781149298f,   -0.0005421323317911481f, \
                  -0.0033824159510061256f }
#define FILT_RH { -0.0033824159510061256f,  0.0005421323317911481f,  0.03169508781149298f,   \
                  -0.007607487324917605f,  -0.1432942383508097f,     0.061273359067658524f,  \
                   0.4813596512583722f,    -0.7771857517005235f,     0.36444189483533895f,   \
                   0.05194583810770904f,   -0.027219029917056003f,  -0.049137179673607506f,  \
                   0.003808752013890615f,   0.01495225833704823f,   -0.0003029205147241331f, \
                  -0.0018899503327594609f }
#define FILT_DLO { -0.0033824159510061256f, -0.0005421323317911481f,  0.03169508781149298f,  \
                    0.007607487324917605f,  -0.1432942383508097f,    -0.061273359067658524f, \
                    0.4813596512583722f,     0.7771857517005235f,     0.36444189483533895f,  \
                   -0.05194583810770904f,   -0.027219029917056003f,   0.049137179673607506f, \
                    0.003808752013890615f,  -0.01495225833704823f,   -0.0003029205147241331f,\
                    0.0018899503327594609f }
#define FILT_DHI { -0.0018899503327594609f, -0.0003029205147241331f,  0.01495225833704823f,  \
                    0.003808752013890615f,  -0.049137179673607506f,  -0.027219029917056003f, \
                    0.05194583810770904f,    0.36444189483533895f,   -0.7771857517005235f,   \
                    0.4813596512583722f,     0.061273359067658524f,  -0.1432942383508097f,   \
                   -0.007607487324917605f,   0.03169508781149298f,    0.0005421323317911481f,\
                   -0.0033824159510061256f }

// 0.85 / 0.6745 * sqrt(2*log(8192))
#define THRSCALE ((float)(0.85 * 4.2452122112874176 / 0.6745))

#define WLO   0.55f
#define WHI   0.80f
#define MBINS 128
#define MCAP  32
#define KRANK 2051

#define PF 8
#define PJ 8

// ---- forward analysis: float2 over channel pairs, stride-2 16-tap ----------
__global__ __launch_bounds__(256) void fwd_kernel(const float* __restrict__ x0,
                                                  int level, int b0) {
    const float* __restrict__ in;
    float* __restrict__ lo;
    float* __restrict__ hi;
    int nin, nout;
    if (level == 1)      { in = x0;    lo = g_lo1; hi = g_hi1; nin = TLEN; nout = N1; }
    else if (level == 2) { in = g_lo1; lo = g_lo2; hi = g_hi2; nin = N1;   nout = N2; }
    else                 { in = g_lo2; lo = g_lo3; hi = g_hi3; nin = N2;   nout = N3; }

    const int b  = b0 + blockIdx.y;
    const int nn = threadIdx.x;
    const int p0 = (blockIdx.x * blockDim.y + threadIdx.y) * PF;
    if (p0 >= nout) return;

    const float RL[16] = FILT_RL;
    const float RH[16] = FILT_RH;

    const float2* __restrict__ inb = reinterpret_cast<const float2*>(in)
                                     + (size_t)(b * nin) * NC2 + nn;
    float2* __restrict__ lo2p = reinterpret_cast<float2*>(lo)
                                + (size_t)(b * nout + p0) * NC2 + nn;
    float2* __restrict__ hi2p = reinterpret_cast<float2*>(hi)
                                + (size_t)(b * nout + p0) * NC2 + nn;

    float2 w[2 * PF + 14];
    const bool interior = (p0 >= 7) && (2 * p0 + 15 < nin) && (p0 + PF <= nout);

    if (interior) {
        const float2* __restrict__ q = inb + (size_t)(2 * p0 - 14) * NC2;
#pragma unroll
        for (int t = 0; t < 2 * PF + 14; ++t)
            w[t] = q[(size_t)t * NC2];
#pragma unroll
        for (int e = 0; e < PF; ++e) {
            float2 alo = {0.f, 0.f}, ahi = {0.f, 0.f};
#pragma unroll
            for (int k = 0; k < 16; ++k) {
                const float2 v = w[2 * e + k];
                alo.x += v.x * RL[k];  alo.y += v.y * RL[k];
                ahi.x += v.x * RH[k];  ahi.y += v.y * RH[k];
            }
            lo2p[(size_t)e * NC2] = alo;
            hi2p[(size_t)e * NC2] = ahi;
        }
    } else {
#pragma unroll
        for (int t = 0; t < 2 * PF + 14; ++t) {
            int i = 2 * p0 - 14 + t;
            if (i < 0)    i = -1 - i;
            if (i >= nin) i = 2 * nin - 1 - i;
            w[t] = inb[(size_t)i * NC2];
        }
#pragma unroll
        for (int e = 0; e < PF; ++e) {
            if (p0 + e < nout) {
                float2 alo = {0.f, 0.f}, ahi = {0.f, 0.f};
#pragma unroll
                for (int k = 0; k < 16; ++k) {
                    const float2 v = w[2 * e + k];
                    alo.x += v.x * RL[k];  alo.y += v.y * RL[k];
                    ahi.x += v.x * RH[k];  ahi.y += v.y * RH[k];
                }
                lo2p[(size_t)e * NC2] = alo;
                hi2p[(size_t)e * NC2] = ahi;
            }
        }
    }
}

// ---- median of |cd1|: SINGLE global pass, smem candidate pool ---------------
// 8 channels/CTA. Pass 1 streams the channel once: counts below-window values
// and stashes all in-window candidates (mean 651/ch, cap 1024 = +16 sigma) in
// smem. Histogram/scan/collect/select then run entirely from smem. Bitwise-
// exact global fallback on any cap/window miss.
#define CPC   8
#define HPAD  9
#define WCAP  1024
__global__ __launch_bounds__(1024) void med_kernel(int b0) {
    __shared__ unsigned int s_wind[CPC * WCAP];     // 32 KB, layout ch + CPC*idx
    __shared__ unsigned int s_hist[MBINS * HPAD];   // 4.6 KB
    __shared__ unsigned int s_below[CPC];
    __shared__ unsigned int s_wcnt[CPC];
    __shared__ unsigned int s_cand[MCAP * CPC];
    __shared__ unsigned int s_cnt[CPC];
    __shared__ int s_tbin[CPC];
    __shared__ int s_krem[CPC];
    __shared__ unsigned int s_fb;
    __shared__ int s_red;

    const int tid   = threadIdx.x;
    const int lane  = tid & 31;
    const int ch    = tid & (CPC - 1);
    const int slice = tid >> 3;                 // 0..127
    const int b     = b0 + blockIdx.y;
    const int n0    = blockIdx.x * CPC;
    const float* __restrict__ base = g_hi1 + (size_t)(b * N1) * NCH + n0 + ch;

    for (int i = tid; i < MBINS * HPAD; i += 1024) s_hist[i] = 0u;
    if (tid < CPC) { s_below[tid] = 0u; s_wcnt[tid] = 0u; s_cnt[tid] = 0u; }
    if (tid == 0) s_fb = 0u;
    __syncthreads();

    // ---- pass 1 (global, ONCE): below count + window candidate stash
    int below = 0;
#pragma unroll 1
    for (int it = 0; it < 4; ++it) {
        float v[8];
#pragma unroll
        for (int q = 0; q < 8; ++q) {
            const int p = slice + 128 * (it * 8 + q);   // < 4096 always
            v[q] = fabsf(__ldg(base + (size_t)p * NCH));
        }
#pragma unroll
        for (int q = 0; q < 8; ++q) {
            below += (v[q] < WLO) ? 1 : 0;
            if (v[q] >= WLO && v[q] < WHI) {
                const unsigned int idx = atomicAdd(&s_wcnt[ch], 1u);
                if (idx < WCAP) s_wind[ch + CPC * idx] = __float_as_uint(v[q]);
            }
        }
    }
    {   // tail: p = slice + 4096, valid for slice < 7
        const int p = slice + 4096;
        if (p < N1) {
            const float v = fabsf(__ldg(base + (size_t)p * NCH));
            below += (v < WLO) ? 1 : 0;
            if (v >= WLO && v < WHI) {
                const unsigned int idx = atomicAdd(&s_wcnt[ch], 1u);
                if (idx < WCAP) s_wind[ch + CPC * idx] = __float_as_uint(v);
            }
        }
    }
    below += __shfl_down_sync(0xffffffffu, below, 16);
    below += __shfl_down_sync(0xffffffffu, below, 8);
    if (lane < CPC) atomicAdd(&s_below[lane], (unsigned int)below);
    __syncthreads();

    if (tid < CPC && s_wcnt[tid] > WCAP) atomicOr(&s_fb, 1u << tid);
    __syncthreads();

    // ---- histogram from smem candidates
    {
        const int wc = (int)s_wcnt[ch] < WCAP ? (int)s_wcnt[ch] : WCAP;
        for (int i = slice; i < wc; i += 128) {
            const float v = __uint_as_float(s_wind[ch + CPC * i]);
            int bin = (int)((v - WLO) * 512.0f);
            bin = bin > (MBINS - 1) ? (MBINS - 1) : bin;
            atomicAdd(&s_hist[bin * HPAD + ch], 1u);
        }
    }
    __syncthreads();

    // ---- scan: target bin per channel
    if (tid < CPC) {
        int rr = KRANK - (int)s_below[tid];
        int t = -1;
        if (rr >= 0) {
            for (int bn = 0; bn < MBINS; ++bn) {
                const int c = (int)s_hist[bn * HPAD + tid];
                if (rr < c) { t = bn; break; }
                rr -= c;
            }
        }
        s_tbin[tid] = t;
        s_krem[tid] = rr;
        if (t < 0) atomicOr(&s_fb, 1u << tid);
    }
    __syncthreads();

    // ---- collect target-bin members from smem
    {
        const int tb = s_tbin[ch];
        const int wc = (int)s_wcnt[ch] < WCAP ? (int)s_wcnt[ch] : WCAP;
        for (int i = slice; i < wc; i += 128) {
            const unsigned int bits = s_wind[ch + CPC * i];
            const float v = __uint_as_float(bits);
            int bin = (int)((v - WLO) * 512.0f);
            bin = bin > (MBINS - 1) ? (MBINS - 1) : bin;
            if (bin == tb) {
                const unsigned int idx = atomicAdd(&s_cnt[ch], 1u);
                if (idx < MCAP) s_cand[idx * CPC + ch] = bits;
            }
        }
    }
    __syncthreads();

    if (tid < CPC && s_cnt[tid] > MCAP) atomicOr(&s_fb, 1u << tid);
    __syncthreads();
    const unsigned int fb = s_fb;

    // ---- exact k-th (with ties) among <=32 candidates, per channel
    if (tid < CPC && !((fb >> tid) & 1u)) {
        const int c = (int)s_cnt[tid];
        const int k = s_krem[tid];
        unsigned int res = 0u;
        for (int i = 0; i < c; ++i) {
            const unsigned int x = s_cand[i * CPC + tid];
            int lt = 0, le = 0;
            for (int jj = 0; jj < c; ++jj) {
                const unsigned int y = s_cand[jj * CPC + tid];
                lt += (y < x);
                le += (y <= x);
            }
            if (lt <= k && k < le) res = x;
        }
        g_thr[b * NCH + n0 + tid] = __uint_as_float(res) * THRSCALE;
    }
    __syncthreads();

    // ---- fallback: exact 32-step bitwise selection (statistically never taken)
    if (fb) {
        for (int c2 = 0; c2 < CPC; ++c2) {
            if (!((fb >> c2) & 1u)) continue;
            const float* __restrict__ bp = g_hi1 + (size_t)(b * N1) * NCH + n0 + c2;
            unsigned int prefix = 0u;
            int kk = KRANK;
            for (int bit = 31; bit >= 0; --bit) {
                if (tid == 0) s_red = 0;
                __syncthreads();
                const unsigned int hi = prefix >> bit;
                int local = 0;
                for (int p = tid; p < N1; p += 1024) {
                    const unsigned int e = __float_as_uint(fabsf(bp[(size_t)p * NCH]));
                    if ((e >> bit) == hi) local++;
                }
                atomicAdd(&s_red, local);
                __syncthreads();
                const int c0 = s_red;
                if (kk >= c0) { kk -= c0; prefix |= (1u << bit); }
                __syncthreads();
            }
            if (tid == 0) g_thr[b * NCH + n0 + c2] = __uint_as_float(prefix) * THRSCALE;
        }
    }
}

// ---- inverse synthesis: float2 over channel pairs, threshold fused ---------
__global__ __launch_bounds__(256) void inv_kernel(float* __restrict__ dout,
                                                  int level, int b0) {
    const float* __restrict__ lo;
    const float* __restrict__ hi;
    float* __restrict__ out;
    int n, nout;
    if (level == 3)      { lo = g_lo3; hi = g_hi3; out = g_lo2; n = N3; nout = N2;   }
    else if (level == 2) { lo = g_lo2; hi = g_hi2; out = g_lo1; n = N2; nout = N1;   }
    else                 { lo = g_lo1; hi = g_hi1; out = dout;  n = N1; nout = TLEN; }

    const int b  = b0 + blockIdx.y;
    const int nn = threadIdx.x;
    const int j0 = (blockIdx.x * blockDim.y + threadIdx.y) * PJ;
    if (2 * j0 >= nout) return;

    const float2 thr = reinterpret_cast<const float2*>(g_thr)[b * NC2 + nn];
    const float DLO[16] = FILT_DLO;
    const float DHI[16] = FILT_DHI;

    const float2* __restrict__ lob = reinterpret_cast<const float2*>(lo)
                                     + (size_t)(b * n) * NC2 + nn;
    const float2* __restrict__ hib = reinterpret_cast<const float2*>(hi)
                                     + (size_t)(b * n) * NC2 + nn;
    float2* __restrict__ ob = reinterpret_cast<float2*>(out)
                              + (size_t)(b * nout) * NC2 + nn;

    float2 wl[PJ + 7], wh[PJ + 7];
    const bool interior = (j0 + PJ + 6 < n) && (2 * (j0 + PJ) <= nout);

    if (interior) {
        const float2* __restrict__ lq = lob + (size_t)j0 * NC2;
        const float2* __restrict__ hq = hib + (size_t)j0 * NC2;
#pragma unroll
        for (int t = 0; t < PJ + 7; ++t) {
            wl[t] = lq[(size_t)t * NC2];
            const float2 h = hq[(size_t)t * NC2];
            const float ax = fabsf(h.x) - thr.x;
            const float ay = fabsf(h.y) - thr.y;
            wh[t].x = (ax > 0.f) ? copysignf(ax, h.x) : 0.f;
            wh[t].y = (ay > 0.f) ? copysignf(ay, h.y) : 0.f;
        }
        float2* __restrict__ op = ob + (size_t)(2 * j0) * NC2;
#pragma unroll
        for (int e = 0; e < PJ; ++e) {
            float2 a0 = {0.f, 0.f}, a1 = {0.f, 0.f};
#pragma unroll
            for (int d = 0; d < 8; ++d) {
                const float2 l = wl[e + d], h = wh[e + d];
                a0.x += l.x * DLO[2 * d + 1] + h.x * DHI[2 * d + 1];
                a0.y += l.y * DLO[2 * d + 1] + h.y * DHI[2 * d + 1];
                a1.x += l.x * DLO[2 * d]     + h.x * DHI[2 * d];
                a1.y += l.y * DLO[2 * d]     + h.y * DHI[2 * d];
            }
            op[(size_t)(2 * e) * NC2]     = a0;
            op[(size_t)(2 * e + 1) * NC2] = a1;
        }
    } else {
#pragma unroll
        for (int t = 0; t < PJ + 7; ++t) {
            int jj = j0 + t;
            if (jj > n - 1) jj = n - 1;
            wl[t] = lob[(size_t)jj * NC2];
            const float2 h = hib[(size_t)jj * NC2];
            const float ax = fabsf(h.x) - thr.x;
            const float ay = fabsf(h.y) - thr.y;
            wh[t].x = (ax > 0.f) ? copysignf(ax, h.x) : 0.f;
            wh[t].y = (ay > 0.f) ? copysignf(ay, h.y) : 0.f;
        }
#pragma unroll
        for (int e = 0; e < PJ; ++e) {
            const int m = 2 * (j0 + e);
            if (m < nout) {
                float2 a0 = {0.f, 0.f}, a1 = {0.f, 0.f};
#pragma unroll
                for (int d = 0; d < 8; ++d) {
                    const float2 l = wl[e + d], h = wh[e + d];
                    a0.x += l.x * DLO[2 * d + 1] + h.x * DHI[2 * d + 1];
                    a0.y += l.y * DLO[2 * d + 1] + h.y * DHI[2 * d + 1];
                    a1.x += l.x * DLO[2 * d]     + h.x * DHI[2 * d];
                    a1.y += l.y * DLO[2 * d]     + h.y * DHI[2 * d];
                }
                ob[(size_t)m * NC2] = a0;
                if (m + 1 < nout) ob[(size_t)(m + 1) * NC2] = a1;
            }
        }
    }
}

// ---- launch: two STAGGERED batch-chunk chains on two streams ----------------
// chunk1 (s2):   fwd1 -> med -> fwd2 -> fwd3 -> inv3 -> inv2 -> inv1
// chunk0 (main): fwd1 -> fwd2 -> fwd3 -> med -> inv3 -> inv2 -> inv1
// Each chain's latency-bound med overlaps the other chain's DRAM-bound convs.
extern "C" void kernel_launch(void* const* d_in, const int* in_sizes, int n_in,
                              void* d_out, int out_size) {
    const float* x = (const float*)d_in[0];
    float* out = (float*)d_out;

    static cudaStream_t s2 = nullptr;
    static cudaEvent_t evF = nullptr, evJ = nullptr;
    if (s2 == nullptr) {
        cudaStreamCreateWithFlags(&s2, cudaStreamNonBlocking);
        cudaEventCreateWithFlags(&evF, cudaEventDisableTiming);
        cudaEventCreateWithFlags(&evJ, cudaEventDisableTiming);
    }

    const dim3 blk(64, 4);   // 64 channel pairs x 4 p-tiles

    cudaEventRecord(evF, 0);
    cudaStreamWaitEvent(s2, evF, 0);

    // chunk 1 on s2: med immediately after fwd1 (stagger)
    fwd_kernel<<<dim3(129, BPC), blk, 0, s2>>>(x, 1, BPC);
    med_kernel<<<dim3(NCH / CPC, BPC), 1024, 0, s2>>>(BPC);
    fwd_kernel<<<dim3( 65, BPC), blk, 0, s2>>>(x, 2, BPC);
    fwd_kernel<<<dim3( 33, BPC), blk, 0, s2>>>(x, 3, BPC);
    inv_kernel<<<dim3( 33, BPC), blk, 0, s2>>>(out, 3, BPC);
    inv_kernel<<<dim3( 65, BPC), blk, 0, s2>>>(out, 2, BPC);
    inv_kernel<<<dim3(128, BPC), blk, 0, s2>>>(out, 1, BPC);
    cudaEventRecord(evJ, s2);

    // chunk 0 on the capture-origin stream: med after fwd3
    fwd_kernel<<<dim3(129, BPC), blk>>>(x, 1, 0);
    fwd_kernel<<<dim3( 65, BPC), blk>>>(x, 2, 0);
    fwd_kernel<<<dim3( 33, BPC), blk>>>(x, 3, 0);
    med_kernel<<<dim3(NCH / CPC, BPC), 1024>>>(0);
    inv_kernel<<<dim3( 33, BPC), blk>>>(out, 3, 0);
    inv_kernel<<<dim3( 65, BPC), blk>>>(out, 2, 0);
    inv_kernel<<<dim3(128, BPC), blk>>>(out, 1, 0);

    cudaStreamWaitEvent(0, evJ, 0);
}